// round 2
// baseline (speedup 1.0000x reference)
#include <cuda_runtime.h>
#include <cuda_bf16.h>
#include <math.h>

// Problem constants
#define BATCH 1024
#define DIN   256
#define HID   512
#define AST   4
#define KOUT  32            // 2*A*A
#define NOUT  (DIN * KOUT)  // 8192

// Scratch hidden activations (allocation-free rule -> __device__ globals)
__device__ float g_h0[BATCH * HID];
__device__ float g_h1[BATCH * HID];
__device__ float g_h2[BATCH * HID];

// ---------------------------------------------------------------------------
// Mask predicates (degrees):
//  MODE 0 (layer0):  hid_deg(n)=n%255 >= in_deg(k)=k
//  MODE 1 (hidden):  n%255 >= k%255
//  MODE 2 (output):  out_deg(n/32)=n/32-1 >= k%255
// ---------------------------------------------------------------------------
template<int MODE>
__device__ __forceinline__ bool maskok(int n, int k) {
    if (MODE == 0) return (n % 255) >= k;
    if (MODE == 1) return (n % 255) >= (k % 255);
    return ((n >> 5) - 1) >= (k % 255);
}

// ---------------------------------------------------------------------------
// 64x64x16 SGEMM (C[M,N] = A[M,K] @ (mask*W)[N,K]^T + bias, optional relu)
// 256 threads, 4x4 per thread. For the small layers (more block parallelism).
// ---------------------------------------------------------------------------
template<int MODE, bool RELU>
__global__ void __launch_bounds__(256) gemm64_kernel(
    const float* __restrict__ A, const float* __restrict__ W,
    const float* __restrict__ bias, float* __restrict__ C,
    int M, int N, int K)
{
    __shared__ float As[16][68];
    __shared__ float Ws[16][68];
    const int bm = blockIdx.y * 64, bn = blockIdx.x * 64;
    const int t  = threadIdx.x;
    const int tx = t & 15, ty = t >> 4;
    const int lr = t >> 2;          // 0..63
    const int lk = (t & 3) * 4;     // 0,4,8,12
    float acc[4][4] = {};

    for (int k0 = 0; k0 < K; k0 += 16) {
        float4 a4 = *(const float4*)(A + (size_t)(bm + lr) * K + k0 + lk);
        float4 w4 = *(const float4*)(W + (size_t)(bn + lr) * K + k0 + lk);
        const float* ap = (const float*)&a4;
        const float* wp = (const float*)&w4;
        #pragma unroll
        for (int q = 0; q < 4; q++) {
            As[lk + q][lr] = ap[q];
            Ws[lk + q][lr] = maskok<MODE>(bn + lr, k0 + lk + q) ? wp[q] : 0.0f;
        }
        __syncthreads();
        #pragma unroll
        for (int kk = 0; kk < 16; kk++) {
            float ra[4], rb[4];
            *(float4*)ra = *(const float4*)&As[kk][ty * 4];
            *(float4*)rb = *(const float4*)&Ws[kk][tx * 4];
            #pragma unroll
            for (int i = 0; i < 4; i++)
                #pragma unroll
                for (int j = 0; j < 4; j++)
                    acc[i][j] = fmaf(ra[i], rb[j], acc[i][j]);
        }
        __syncthreads();
    }

    #pragma unroll
    for (int i = 0; i < 4; i++) {
        const int m = bm + ty * 4 + i;
        float4 v; float* vp = (float*)&v;
        #pragma unroll
        for (int j = 0; j < 4; j++) {
            const int n = bn + tx * 4 + j;
            float val = acc[i][j] + bias[n];
            vp[j] = RELU ? fmaxf(val, 0.0f) : val;
        }
        *(float4*)(C + (size_t)m * N + bn + tx * 4) = v;
    }
}

// ---------------------------------------------------------------------------
// 128x128x8 SGEMM, 256 threads, 8x8 per thread. For the big output GEMM.
// ---------------------------------------------------------------------------
template<int MODE, bool RELU>
__global__ void __launch_bounds__(256) gemm128_kernel(
    const float* __restrict__ A, const float* __restrict__ W,
    const float* __restrict__ bias, float* __restrict__ C,
    int M, int N, int K)
{
    __shared__ float As[8][132];
    __shared__ float Ws[8][132];
    const int bm = blockIdx.y * 128, bn = blockIdx.x * 128;
    const int t  = threadIdx.x;
    const int tx = t & 15, ty = t >> 4;
    const int lr = t >> 1;          // 0..127
    const int lk = (t & 1) * 4;     // 0 or 4
    float acc[8][8] = {};

    for (int k0 = 0; k0 < K; k0 += 8) {
        float4 a4 = *(const float4*)(A + (size_t)(bm + lr) * K + k0 + lk);
        float4 w4 = *(const float4*)(W + (size_t)(bn + lr) * K + k0 + lk);
        const float* ap = (const float*)&a4;
        const float* wp = (const float*)&w4;
        #pragma unroll
        for (int q = 0; q < 4; q++) {
            As[lk + q][lr] = ap[q];
            Ws[lk + q][lr] = maskok<MODE>(bn + lr, k0 + lk + q) ? wp[q] : 0.0f;
        }
        __syncthreads();
        #pragma unroll
        for (int kk = 0; kk < 8; kk++) {
            float ra[8], rb[8];
            *(float4*)&ra[0] = *(const float4*)&As[kk][ty * 8];
            *(float4*)&ra[4] = *(const float4*)&As[kk][ty * 8 + 4];
            *(float4*)&rb[0] = *(const float4*)&Ws[kk][tx * 8];
            *(float4*)&rb[4] = *(const float4*)&Ws[kk][tx * 8 + 4];
            #pragma unroll
            for (int i = 0; i < 8; i++)
                #pragma unroll
                for (int j = 0; j < 8; j++)
                    acc[i][j] = fmaf(ra[i], rb[j], acc[i][j]);
        }
        __syncthreads();
    }

    #pragma unroll
    for (int i = 0; i < 8; i++) {
        const int m = bm + ty * 8 + i;
        #pragma unroll
        for (int jj = 0; jj < 2; jj++) {
            float4 v; float* vp = (float*)&v;
            #pragma unroll
            for (int q = 0; q < 4; q++) {
                const int j = jj * 4 + q;
                const int n = bn + tx * 8 + j;
                float val = acc[i][j] + bias[n];
                vp[q] = RELU ? fmaxf(val, 0.0f) : val;
            }
            *(float4*)(C + (size_t)m * N + bn + tx * 8 + jj * 4) = v;
        }
    }
}

// ---------------------------------------------------------------------------
// Fused log_px + forward-chain kernel.
// 16 lanes per batch (lane l = i*4+j), 2 batches per warp.
// carry[j] lives replicated on lanes with l%4==j.
// ---------------------------------------------------------------------------
__global__ void __launch_bounds__(256) chain_kernel(
    const float* __restrict__ x, const float* __restrict__ theta,
    const float* __restrict__ ulpa, float* __restrict__ out)
{
    __shared__ float s_lpa[255 * 4];
    // Precompute lpa = log_softmax(ulpa) per (d, j)
    for (int d = threadIdx.x; d < 255; d += blockDim.x) {
        float u0 = ulpa[d * 4 + 0], u1 = ulpa[d * 4 + 1];
        float u2 = ulpa[d * 4 + 2], u3 = ulpa[d * 4 + 3];
        float m = fmaxf(fmaxf(u0, u1), fmaxf(u2, u3));
        float s = expf(u0 - m) + expf(u1 - m) + expf(u2 - m) + expf(u3 - m);
        float lse = m + logf(s);
        s_lpa[d * 4 + 0] = u0 - lse;
        s_lpa[d * 4 + 1] = u1 - lse;
        s_lpa[d * 4 + 2] = u2 - lse;
        s_lpa[d * 4 + 3] = u3 - lse;
    }
    __syncthreads();

    const int lane = threadIdx.x & 31;
    const int wid  = threadIdx.x >> 5;
    const int half = lane >> 4;    // which batch within the warp
    const int l    = lane & 15;    // 0..15
    const int i    = l >> 2, j = l & 3;
    const int b    = (blockIdx.x * 8 + wid) * 2 + half;

    const unsigned FULL = 0xffffffffu;
    const float NLOG2PI2 = -0.91893853320467274178f;  // -0.5*log(2*pi)

    const float* th = theta + (size_t)b * DIN * KOUT;
    const float* xb = x + (size_t)b * DIN;

    float carry = 0.0f;
    for (int d = 0; d < DIN; d++) {
        float mu = th[d * 32 + l];
        float ls = th[d * 32 + 16 + l];
        float xd = xb[d];
        float sd = expf(ls) + 0.01f;
        float z  = (xd - mu) / sd;
        float lp = fmaf(-0.5f * z, z, NLOG2PI2) - logf(sd);

        if (d == 0) {
            // first = joint[:,0, i=0, j]
            float v = lp + s_lpa[j];
            carry = __shfl_sync(FULL, v, half * 16 + j);
        } else if (d < 255) {
            // new[j] = LSE_i( carry[i] + log_px[d,i,j] + lpa[d,j] )
            float ci = __shfl_sync(FULL, carry, half * 16 + i);
            float tv = ci + lp + s_lpa[d * 4 + j];
            float m = tv;
            m = fmaxf(m, __shfl_xor_sync(FULL, m, 4));
            m = fmaxf(m, __shfl_xor_sync(FULL, m, 8));
            float s = expf(tv - m);
            s += __shfl_xor_sync(FULL, s, 4);
            s += __shfl_xor_sync(FULL, s, 8);
            carry = m + logf(s);
        } else {
            // log_p = LSE_i( carry[i] + log_px[255, i, 0] )
            float ci = __shfl_sync(FULL, carry, half * 16 + i);
            float tv = (j == 0) ? (ci + lp) : -1e30f;
            float m = tv;
            m = fmaxf(m, __shfl_xor_sync(FULL, m, 1));
            m = fmaxf(m, __shfl_xor_sync(FULL, m, 2));
            m = fmaxf(m, __shfl_xor_sync(FULL, m, 4));
            m = fmaxf(m, __shfl_xor_sync(FULL, m, 8));
            float s = expf(tv - m);
            s += __shfl_xor_sync(FULL, s, 1);
            s += __shfl_xor_sync(FULL, s, 2);
            s += __shfl_xor_sync(FULL, s, 4);
            s += __shfl_xor_sync(FULL, s, 8);
            if (l == 0) out[b] = m + logf(s);
        }
    }
}

// ---------------------------------------------------------------------------
// kernel_launch
// Inputs (metadata order): x, W0, b0, W1, b1, W2, b2, Wout, bout, ulpa
// Output layout: [log_p (1024) | theta (1024*256*32)] (leaf order of the tuple)
// ---------------------------------------------------------------------------
extern "C" void kernel_launch(void* const* d_in, const int* in_sizes, int n_in,
                              void* d_out, int out_size)
{
    const float* x    = (const float*)d_in[0];
    const float* W0   = (const float*)d_in[1];
    const float* b0   = (const float*)d_in[2];
    const float* W1   = (const float*)d_in[3];
    const float* b1   = (const float*)d_in[4];
    const float* W2   = (const float*)d_in[5];
    const float* b2   = (const float*)d_in[6];
    const float* Wout = (const float*)d_in[7];
    const float* bout = (const float*)d_in[8];
    const float* ulpa = (const float*)d_in[9];

    float* out   = (float*)d_out;
    float* theta = out + BATCH;   // log_p first, then theta

    float *h0, *h1, *h2;
    cudaGetSymbolAddress((void**)&h0, g_h0);
    cudaGetSymbolAddress((void**)&h1, g_h1);
    cudaGetSymbolAddress((void**)&h2, g_h2);

    // Layer 0: [1024,256] x [512,256]^T (mask m0), relu
    gemm64_kernel<0, true><<<dim3(HID / 64, BATCH / 64), 256>>>(
        x, W0, b0, h0, BATCH, HID, DIN);
    // Layers 1,2: [1024,512] x [512,512]^T (mask mh), relu
    gemm64_kernel<1, true><<<dim3(HID / 64, BATCH / 64), 256>>>(
        h0, W1, b1, h1, BATCH, HID, HID);
    gemm64_kernel<1, true><<<dim3(HID / 64, BATCH / 64), 256>>>(
        h1, W2, b2, h2, BATCH, HID, HID);
    // Output layer: [1024,512] x [8192,512]^T (mask ml), no relu -> theta
    gemm128_kernel<2, false><<<dim3(NOUT / 128, BATCH / 128), 256>>>(
        h2, Wout, bout, theta, BATCH, NOUT, HID);
    // Chain: log_px + forward scan -> log_p
    chain_kernel<<<BATCH / 16, 256>>>(x, theta, ulpa, out);
}

// round 4
// speedup vs baseline: 1.2882x; 1.2882x over previous
#include <cuda_runtime.h>
#include <cuda_bf16.h>
#include <math.h>
#include <stdint.h>

// Problem constants
#define BATCH 1024
#define DIN   256
#define HID   512
#define KOUT  32            // 2*A*A
#define NOUT  (DIN * KOUT)  // 8192

// Scratch (allocation-free rule -> __device__ globals)
__device__ float g_h0[BATCH * HID];
__device__ float g_h1[BATCH * HID];
__device__ float g_h2[BATCH * HID];
__device__ __nv_bfloat16 g_hhi[BATCH * HID];
__device__ __nv_bfloat16 g_hlo[BATCH * HID];
__device__ __nv_bfloat16 g_whi[NOUT * HID];
__device__ __nv_bfloat16 g_wlo[NOUT * HID];

// ---------------------------------------------------------------------------
// Helpers: ldmatrix + mma.sync (arch-baseline tensor path; tcgen05 is not
// accepted by this toolchain's compute_103 PTX stage)
// ---------------------------------------------------------------------------
__device__ __forceinline__ uint32_t smem_u32(const void* p) {
    uint32_t a;
    asm("{ .reg .u64 t; cvta.to.shared.u64 t, %1; cvt.u32.u64 %0, t; }" : "=r"(a) : "l"(p));
    return a;
}
__device__ __forceinline__ void ldm_x4(uint32_t* r, uint32_t addr) {
    asm volatile("ldmatrix.sync.aligned.m8n8.x4.shared.b16 {%0,%1,%2,%3}, [%4];"
                 : "=r"(r[0]), "=r"(r[1]), "=r"(r[2]), "=r"(r[3]) : "r"(addr));
}
__device__ __forceinline__ void mma_bf16(float* d, const uint32_t* a, const uint32_t* b) {
    asm volatile("mma.sync.aligned.m16n8k16.row.col.f32.bf16.bf16.f32 "
                 "{%0,%1,%2,%3}, {%4,%5,%6,%7}, {%8,%9}, {%0,%1,%2,%3};"
                 : "+f"(d[0]), "+f"(d[1]), "+f"(d[2]), "+f"(d[3])
                 : "r"(a[0]), "r"(a[1]), "r"(a[2]), "r"(a[3]), "r"(b[0]), "r"(b[1]));
}

// ---------------------------------------------------------------------------
// Mask predicates
// ---------------------------------------------------------------------------
template<int MODE>
__device__ __forceinline__ bool maskok(int n, int k) {
    if (MODE == 0) return (n % 255) >= k;
    if (MODE == 1) return (n % 255) >= (k % 255);
    return ((n >> 5) - 1) >= (k % 255);
}

// ---------------------------------------------------------------------------
// Split kernels: fp32 -> bf16 hi/lo (mask folded in for Wout)
// ---------------------------------------------------------------------------
__global__ void __launch_bounds__(256) split_w_kernel(
    const float* __restrict__ W, __nv_bfloat16* __restrict__ hi,
    __nv_bfloat16* __restrict__ lo)
{
    int idx = blockIdx.x * blockDim.x + threadIdx.x;  // 4 elems each
    int base = idx * 4;
    if (base >= NOUT * HID) return;
    int n = base / HID, k = base % HID;
    int od = (n >> 5) - 1;
    float4 w4 = *(const float4*)(W + base);
    float wv[4] = {w4.x, w4.y, w4.z, w4.w};
    __nv_bfloat16 h[4], l[4];
    #pragma unroll
    for (int q = 0; q < 4; q++) {
        float wm = (od >= ((k + q) % 255)) ? wv[q] : 0.0f;
        h[q] = __float2bfloat16(wm);
        l[q] = __float2bfloat16(wm - __bfloat162float(h[q]));
    }
    *(uint2*)(hi + base) = *(uint2*)h;
    *(uint2*)(lo + base) = *(uint2*)l;
}

__global__ void __launch_bounds__(256) split_h_kernel(
    const float* __restrict__ H, __nv_bfloat16* __restrict__ hi,
    __nv_bfloat16* __restrict__ lo)
{
    int idx = blockIdx.x * blockDim.x + threadIdx.x;
    int base = idx * 4;
    if (base >= BATCH * HID) return;
    float4 w4 = *(const float4*)(H + base);
    float wv[4] = {w4.x, w4.y, w4.z, w4.w};
    __nv_bfloat16 h[4], l[4];
    #pragma unroll
    for (int q = 0; q < 4; q++) {
        h[q] = __float2bfloat16(wv[q]);
        l[q] = __float2bfloat16(wv[q] - __bfloat162float(h[q]));
    }
    *(uint2*)(hi + base) = *(uint2*)h;
    *(uint2*)(lo + base) = *(uint2*)l;
}

// ---------------------------------------------------------------------------
// HMMA split-precision GEMM: theta[1024,8192] = h2 @ (ml*Wout)^T + bout
// Tiles 128x128x32; 8 warps as 2(m) x 4(n); per-warp 64x32.
// 3 accumulation terms: Ahi*Whi + Alo*Whi + Ahi*Wlo (all fp32 acc).
// ---------------------------------------------------------------------------
#define BMM 128
#define BNN 128
#define BKK 32
#define LDT 40   // padded row length in bf16 (80B stride -> conflict-free ldmatrix)

__global__ void __launch_bounds__(256, 2) gemm_mma_kernel(
    const __nv_bfloat16* __restrict__ Ahi, const __nv_bfloat16* __restrict__ Alo,
    const __nv_bfloat16* __restrict__ Whi, const __nv_bfloat16* __restrict__ Wlo,
    const float* __restrict__ bias, float* __restrict__ C)
{
    __shared__ __nv_bfloat16 Asm[BMM * LDT];
    __shared__ __nv_bfloat16 Wsm[BNN * LDT];

    const int tid  = threadIdx.x;
    const int lane = tid & 31;
    const int wrp  = tid >> 5;
    const int wm   = wrp >> 2;       // 0..1
    const int wn   = wrp & 3;        // 0..3
    const int bm   = blockIdx.y * BMM;
    const int bn   = blockIdx.x * BNN;

    const uint32_t sA = smem_u32(Asm);
    const uint32_t sW = smem_u32(Wsm);

    // ldmatrix address templates (byte offsets, k16 added in loop)
    uint32_t addrA[4];
    #pragma unroll
    for (int mi = 0; mi < 4; mi++) {
        int row = wm * 64 + mi * 16 + (lane & 15);
        int kof = (lane >> 4) * 8;
        addrA[mi] = sA + (uint32_t)(row * LDT + kof) * 2u;
    }
    uint32_t addrB[2];
    {
        int mat = lane >> 3;
        #pragma unroll
        for (int p = 0; p < 2; p++) {
            int n   = wn * 32 + p * 16 + ((mat >> 1) << 3) + (lane & 7);
            int kof = (mat & 1) * 8;
            addrB[p] = sW + (uint32_t)(n * LDT + kof) * 2u;
        }
    }

    float acc[4][4][4];
    #pragma unroll
    for (int i = 0; i < 4; i++)
        #pragma unroll
        for (int j = 0; j < 4; j++)
            #pragma unroll
            for (int q = 0; q < 4; q++) acc[i][j][q] = 0.0f;

    #pragma unroll 1
    for (int term = 0; term < 3; term++) {
        const __nv_bfloat16* Ap = (term == 1) ? Alo : Ahi;
        const __nv_bfloat16* Wp = (term == 2) ? Wlo : Whi;

        #pragma unroll 1
        for (int kc = 0; kc < HID; kc += BKK) {
            __syncthreads();
            // Load A,W tiles: 128x32 bf16 each; 512 8-elem segments per tile.
            #pragma unroll
            for (int i = 0; i < 2; i++) {
                int idx = tid + i * 256;
                int row = idx >> 2, c8 = (idx & 3) * 8;
                *(int4*)&Asm[row * LDT + c8] =
                    *(const int4*)&Ap[(size_t)(bm + row) * HID + kc + c8];
                *(int4*)&Wsm[row * LDT + c8] =
                    *(const int4*)&Wp[(size_t)(bn + row) * HID + kc + c8];
            }
            __syncthreads();

            #pragma unroll
            for (int k16 = 0; k16 < BKK; k16 += 16) {
                uint32_t a[4][4], b[2][4];
                #pragma unroll
                for (int mi = 0; mi < 4; mi++)
                    ldm_x4(a[mi], addrA[mi] + (uint32_t)k16 * 2u);
                #pragma unroll
                for (int p = 0; p < 2; p++)
                    ldm_x4(b[p], addrB[p] + (uint32_t)k16 * 2u);
                #pragma unroll
                for (int mi = 0; mi < 4; mi++) {
                    #pragma unroll
                    for (int p = 0; p < 2; p++) {
                        mma_bf16(acc[mi][p * 2 + 0], a[mi], &b[p][0]);
                        mma_bf16(acc[mi][p * 2 + 1], a[mi], &b[p][2]);
                    }
                }
            }
        }
    }

    // Epilogue: add bias, store fp32
    const int r0 = bm + wm * 64 + (lane >> 2);
    const int cbase = bn + wn * 32 + (lane & 3) * 2;
    #pragma unroll
    for (int mi = 0; mi < 4; mi++) {
        #pragma unroll
        for (int nj = 0; nj < 4; nj++) {
            const int col = cbase + nj * 8;
            const float b0 = bias[col], b1 = bias[col + 1];
            float2 v0 = {acc[mi][nj][0] + b0, acc[mi][nj][1] + b1};
            float2 v1 = {acc[mi][nj][2] + b0, acc[mi][nj][3] + b1};
            *(float2*)(C + (size_t)(r0 + mi * 16) * NOUT + col)     = v0;
            *(float2*)(C + (size_t)(r0 + mi * 16 + 8) * NOUT + col) = v1;
        }
    }
}

// ---------------------------------------------------------------------------
// 64x64x16 SGEMM for the small masked layers
// ---------------------------------------------------------------------------
template<int MODE, bool RELU>
__global__ void __launch_bounds__(256) gemm64_kernel(
    const float* __restrict__ A, const float* __restrict__ W,
    const float* __restrict__ bias, float* __restrict__ C,
    int M, int N, int K)
{
    __shared__ float As[16][68];
    __shared__ float Ws[16][68];
    const int bm = blockIdx.y * 64, bn = blockIdx.x * 64;
    const int t  = threadIdx.x;
    const int tx = t & 15, ty = t >> 4;
    const int lr = t >> 2;
    const int lk = (t & 3) * 4;
    float acc[4][4] = {};

    for (int k0 = 0; k0 < K; k0 += 16) {
        float4 a4 = *(const float4*)(A + (size_t)(bm + lr) * K + k0 + lk);
        float4 w4 = *(const float4*)(W + (size_t)(bn + lr) * K + k0 + lk);
        const float* ap = (const float*)&a4;
        const float* wp = (const float*)&w4;
        #pragma unroll
        for (int q = 0; q < 4; q++) {
            As[lk + q][lr] = ap[q];
            Ws[lk + q][lr] = maskok<MODE>(bn + lr, k0 + lk + q) ? wp[q] : 0.0f;
        }
        __syncthreads();
        #pragma unroll
        for (int kk = 0; kk < 16; kk++) {
            float ra[4], rb[4];
            *(float4*)ra = *(const float4*)&As[kk][ty * 4];
            *(float4*)rb = *(const float4*)&Ws[kk][tx * 4];
            #pragma unroll
            for (int i = 0; i < 4; i++)
                #pragma unroll
                for (int j = 0; j < 4; j++)
                    acc[i][j] = fmaf(ra[i], rb[j], acc[i][j]);
        }
        __syncthreads();
    }

    #pragma unroll
    for (int i = 0; i < 4; i++) {
        const int m = bm + ty * 4 + i;
        float4 v; float* vp = (float*)&v;
        #pragma unroll
        for (int j = 0; j < 4; j++) {
            const int n = bn + tx * 4 + j;
            float val = acc[i][j] + bias[n];
            vp[j] = RELU ? fmaxf(val, 0.0f) : val;
        }
        *(float4*)(C + (size_t)m * N + bn + tx * 4) = v;
    }
}

// ---------------------------------------------------------------------------
// Fused log_px + forward-chain kernel
// ---------------------------------------------------------------------------
__global__ void __launch_bounds__(256) chain_kernel(
    const float* __restrict__ x, const float* __restrict__ theta,
    const float* __restrict__ ulpa, float* __restrict__ out)
{
    __shared__ float s_lpa[255 * 4];
    for (int d = threadIdx.x; d < 255; d += blockDim.x) {
        float u0 = ulpa[d * 4 + 0], u1 = ulpa[d * 4 + 1];
        float u2 = ulpa[d * 4 + 2], u3 = ulpa[d * 4 + 3];
        float m = fmaxf(fmaxf(u0, u1), fmaxf(u2, u3));
        float s = expf(u0 - m) + expf(u1 - m) + expf(u2 - m) + expf(u3 - m);
        float lse = m + logf(s);
        s_lpa[d * 4 + 0] = u0 - lse;
        s_lpa[d * 4 + 1] = u1 - lse;
        s_lpa[d * 4 + 2] = u2 - lse;
        s_lpa[d * 4 + 3] = u3 - lse;
    }
    __syncthreads();

    const int lane = threadIdx.x & 31;
    const int wid  = threadIdx.x >> 5;
    const int half = lane >> 4;
    const int l    = lane & 15;
    const int i    = l >> 2, j = l & 3;
    const int b    = (blockIdx.x * 8 + wid) * 2 + half;

    const unsigned FULL = 0xffffffffu;
    const float NLOG2PI2 = -0.91893853320467274178f;

    const float* th = theta + (size_t)b * DIN * KOUT;
    const float* xb = x + (size_t)b * DIN;

    float carry = 0.0f;
    for (int d = 0; d < DIN; d++) {
        float mu = th[d * 32 + l];
        float ls = th[d * 32 + 16 + l];
        float xd = xb[d];
        float sd = expf(ls) + 0.01f;
        float z  = (xd - mu) / sd;
        float lp = fmaf(-0.5f * z, z, NLOG2PI2) - logf(sd);

        if (d == 0) {
            float v = lp + s_lpa[j];
            carry = __shfl_sync(FULL, v, half * 16 + j);
        } else if (d < 255) {
            float ci = __shfl_sync(FULL, carry, half * 16 + i);
            float tv = ci + lp + s_lpa[d * 4 + j];
            float m = tv;
            m = fmaxf(m, __shfl_xor_sync(FULL, m, 4));
            m = fmaxf(m, __shfl_xor_sync(FULL, m, 8));
            float s = expf(tv - m);
            s += __shfl_xor_sync(FULL, s, 4);
            s += __shfl_xor_sync(FULL, s, 8);
            carry = m + logf(s);
        } else {
            float ci = __shfl_sync(FULL, carry, half * 16 + i);
            float tv = (j == 0) ? (ci + lp) : -1e30f;
            float m = tv;
            m = fmaxf(m, __shfl_xor_sync(FULL, m, 1));
            m = fmaxf(m, __shfl_xor_sync(FULL, m, 2));
            m = fmaxf(m, __shfl_xor_sync(FULL, m, 4));
            m = fmaxf(m, __shfl_xor_sync(FULL, m, 8));
            float s = expf(tv - m);
            s += __shfl_xor_sync(FULL, s, 1);
            s += __shfl_xor_sync(FULL, s, 2);
            s += __shfl_xor_sync(FULL, s, 4);
            s += __shfl_xor_sync(FULL, s, 8);
            if (l == 0) out[b] = m + logf(s);
        }
    }
}

// ---------------------------------------------------------------------------
// kernel_launch
// ---------------------------------------------------------------------------
extern "C" void kernel_launch(void* const* d_in, const int* in_sizes, int n_in,
                              void* d_out, int out_size)
{
    const float* x    = (const float*)d_in[0];
    const float* W0   = (const float*)d_in[1];
    const float* b0   = (const float*)d_in[2];
    const float* W1   = (const float*)d_in[3];
    const float* b1   = (const float*)d_in[4];
    const float* W2   = (const float*)d_in[5];
    const float* b2   = (const float*)d_in[6];
    const float* Wout = (const float*)d_in[7];
    const float* bout = (const float*)d_in[8];
    const float* ulpa = (const float*)d_in[9];

    float* out   = (float*)d_out;
    float* theta = out + BATCH;

    float *h0, *h1, *h2;
    __nv_bfloat16 *hhi, *hlo, *whi, *wlo;
    cudaGetSymbolAddress((void**)&h0, g_h0);
    cudaGetSymbolAddress((void**)&h1, g_h1);
    cudaGetSymbolAddress((void**)&h2, g_h2);
    cudaGetSymbolAddress((void**)&hhi, g_hhi);
    cudaGetSymbolAddress((void**)&hlo, g_hlo);
    cudaGetSymbolAddress((void**)&whi, g_whi);
    cudaGetSymbolAddress((void**)&wlo, g_wlo);

    // Wout mask+split (independent of activations)
    split_w_kernel<<<(NOUT * HID / 4 + 255) / 256, 256>>>(Wout, whi, wlo);

    gemm64_kernel<0, true><<<dim3(HID / 64, BATCH / 64), 256>>>(
        x, W0, b0, h0, BATCH, HID, DIN);
    gemm64_kernel<1, true><<<dim3(HID / 64, BATCH / 64), 256>>>(
        h0, W1, b1, h1, BATCH, HID, HID);
    gemm64_kernel<1, true><<<dim3(HID / 64, BATCH / 64), 256>>>(
        h1, W2, b2, h2, BATCH, HID, HID);

    split_h_kernel<<<(BATCH * HID / 4 + 255) / 256, 256>>>(h2, hhi, hlo);

    gemm_mma_kernel<<<dim3(NOUT / BNN, BATCH / BMM), 256>>>(
        hhi, hlo, whi, wlo, bout, theta);

    chain_kernel<<<BATCH / 16, 256>>>(x, theta, ulpa, out);
}

// round 5
// speedup vs baseline: 1.6790x; 1.3034x over previous
#include <cuda_runtime.h>
#include <cuda_bf16.h>
#include <math.h>
#include <stdint.h>

#define BATCH 1024
#define DIN   256
#define HID   512
#define KOUT  32
#define NOUT  (DIN * KOUT)  // 8192

typedef __nv_bfloat16 bf16;

// Scratch (allocation-free rule -> __device__ globals)
__device__ bf16 g_xhi[BATCH * DIN],  g_xlo[BATCH * DIN];
__device__ bf16 g_w0hi[HID * DIN],   g_w0lo[HID * DIN];
__device__ bf16 g_w1hi[HID * HID],   g_w1lo[HID * HID];
__device__ bf16 g_w2hi[HID * HID],   g_w2lo[HID * HID];
__device__ bf16 g_h0hi[BATCH * HID], g_h0lo[BATCH * HID];
__device__ bf16 g_h1hi[BATCH * HID], g_h1lo[BATCH * HID];
__device__ bf16 g_h2hi[BATCH * HID], g_h2lo[BATCH * HID];
__device__ bf16 g_whi[NOUT * HID],   g_wlo[NOUT * HID];

// ---------------------------------------------------------------------------
// PTX helpers (sm_80-baseline: ldmatrix / mma.sync / cp.async — tcgen05 is
// rejected by this toolchain's compute_103 stage)
// ---------------------------------------------------------------------------
__device__ __forceinline__ uint32_t smem_u32(const void* p) {
    uint32_t a;
    asm("{ .reg .u64 t; cvta.to.shared.u64 t, %1; cvt.u32.u64 %0, t; }" : "=r"(a) : "l"(p));
    return a;
}
__device__ __forceinline__ void ldm_x4(uint32_t* r, uint32_t addr) {
    asm volatile("ldmatrix.sync.aligned.m8n8.x4.shared.b16 {%0,%1,%2,%3}, [%4];"
                 : "=r"(r[0]), "=r"(r[1]), "=r"(r[2]), "=r"(r[3]) : "r"(addr));
}
__device__ __forceinline__ void mma_bf16(float* d, const uint32_t* a, const uint32_t* b) {
    asm volatile("mma.sync.aligned.m16n8k16.row.col.f32.bf16.bf16.f32 "
                 "{%0,%1,%2,%3}, {%4,%5,%6,%7}, {%8,%9}, {%0,%1,%2,%3};"
                 : "+f"(d[0]), "+f"(d[1]), "+f"(d[2]), "+f"(d[3])
                 : "r"(a[0]), "r"(a[1]), "r"(a[2]), "r"(a[3]), "r"(b[0]), "r"(b[1]));
}
__device__ __forceinline__ void cp16(uint32_t dst, const void* src) {
    asm volatile("cp.async.cg.shared.global [%0], [%1], 16;" :: "r"(dst), "l"(src) : "memory");
}
__device__ __forceinline__ void cp_commit() {
    asm volatile("cp.async.commit_group;" ::: "memory");
}
template<int N> __device__ __forceinline__ void cp_wait() {
    asm volatile("cp.async.wait_group %0;" :: "n"(N) : "memory");
}
__device__ __forceinline__ void split2(float v, bf16& h, bf16& l) {
    h = __float2bfloat16(v);
    l = __float2bfloat16(v - __bfloat162float(h));
}

// ---------------------------------------------------------------------------
// Prep: split x, W0, W1, W2 into bf16 hi/lo with masks folded in.
// Regions by global thread id (4 floats per thread).
// ---------------------------------------------------------------------------
__global__ void __launch_bounds__(256) prep_kernel(
    const float* __restrict__ x,  const float* __restrict__ W0,
    const float* __restrict__ W1, const float* __restrict__ W2)
{
    int t = blockIdx.x * 256 + threadIdx.x;
    const float* src; bf16 *hi, *lo;
    int mode, ksh, base;
    if (t < 65536)       { src = x;  hi = g_xhi;  lo = g_xlo;  mode = -1; ksh = 8; base = t * 4; }
    else if (t < 98304)  { src = W0; hi = g_w0hi; lo = g_w0lo; mode = 0;  ksh = 8; base = (t - 65536) * 4; }
    else if (t < 163840) { src = W1; hi = g_w1hi; lo = g_w1lo; mode = 1;  ksh = 9; base = (t - 98304) * 4; }
    else                 { src = W2; hi = g_w2hi; lo = g_w2lo; mode = 1;  ksh = 9; base = (t - 163840) * 4; }

    float4 v4 = *(const float4*)(src + base);
    float vv[4] = {v4.x, v4.y, v4.z, v4.w};
    int n = base >> ksh;
    int k0 = base & ((1 << ksh) - 1);
    int nd = n % 255;
    bf16 h[4], l[4];
    #pragma unroll
    for (int q = 0; q < 4; q++) {
        float v = vv[q];
        int k = k0 + q;
        if (mode == 0 && !(nd >= k)) v = 0.0f;
        if (mode == 1 && !(nd >= (k % 255))) v = 0.0f;
        split2(v, h[q], l[q]);
    }
    *(uint2*)(hi + base) = *(uint2*)h;
    *(uint2*)(lo + base) = *(uint2*)l;
}

// Wout split with output mask (MODE 2)
__global__ void __launch_bounds__(256) split_wout_kernel(const float* __restrict__ W)
{
    int idx = blockIdx.x * 256 + threadIdx.x;
    int base = idx * 4;
    int n = base >> 9, k0 = base & 511;
    int od = (n >> 5) - 1;
    float4 w4 = *(const float4*)(W + base);
    float wv[4] = {w4.x, w4.y, w4.z, w4.w};
    bf16 h[4], l[4];
    #pragma unroll
    for (int q = 0; q < 4; q++) {
        float v = (od >= ((k0 + q) % 255)) ? wv[q] : 0.0f;
        split2(v, h[q], l[q]);
    }
    *(uint2*)(g_whi + base) = *(uint2*)h;
    *(uint2*)(g_wlo + base) = *(uint2*)l;
}

// ---------------------------------------------------------------------------
// Small-layer HMMA kernel: C = relu(A @ W^T + b), split epilogue -> Chi/Clo.
// A: [1024,K] hi/lo bf16, W: [512,K] hi/lo bf16 (mask pre-folded).
// Tile 64x64, BK=32, 128 threads (4 warps, warp = 64m x 16n), cp.async x2.
// Smem tile rows: 64B, XOR swizzle chunk c' = c ^ ((r>>1)&3) (conflict-free).
// ---------------------------------------------------------------------------
template<int K>
__global__ void __launch_bounds__(128) layer_kernel(
    const bf16* __restrict__ Ahi, const bf16* __restrict__ Alo,
    const bf16* __restrict__ Whi, const bf16* __restrict__ Wlo,
    const float* __restrict__ bias,
    bf16* __restrict__ Chi, bf16* __restrict__ Clo)
{
    __shared__ bf16 sm[2 * 4 * 64 * 32];
    const int tid = threadIdx.x, lane = tid & 31, wn = tid >> 5;
    const int bm = blockIdx.y * 64, bn = blockIdx.x * 64;
    const uint32_t sb = smem_u32(sm);
    const int NC = K / 32;

    auto load_stage = [&](int s, int kc) {
        uint32_t stg = sb + (uint32_t)s * 16384u;
        #pragma unroll
        for (int i = 0; i < 2; i++) {
            int idx = tid + i * 128;
            int r = idx >> 2, c = idx & 3;
            uint32_t dsw = (uint32_t)(r * 64 + ((c ^ ((r >> 1) & 3)) << 4));
            size_t asrc = (size_t)(bm + r) * K + kc * 32 + c * 8;
            size_t wsrc = (size_t)(bn + r) * K + kc * 32 + c * 8;
            cp16(stg + dsw,          Ahi + asrc);
            cp16(stg + 4096u + dsw,  Alo + asrc);
            cp16(stg + 8192u + dsw,  Whi + wsrc);
            cp16(stg + 12288u + dsw, Wlo + wsrc);
        }
    };

    // frag address components
    int raby[4], swa[4];
    #pragma unroll
    for (int mi = 0; mi < 4; mi++) {
        int r = mi * 16 + (lane & 15);
        raby[mi] = r * 64;
        swa[mi] = (r >> 1) & 3;
    }
    const int hiA = lane >> 4;
    const int nloc = wn * 16 + (((lane >> 3) >> 1) << 3) + (lane & 7);
    const int rbby = nloc * 64, swb = (nloc >> 1) & 3, cbB = (lane >> 3) & 1;

    float acc[4][2][4];
    #pragma unroll
    for (int a = 0; a < 4; a++)
        #pragma unroll
        for (int bq = 0; bq < 2; bq++)
            #pragma unroll
            for (int q = 0; q < 4; q++) acc[a][bq][q] = 0.0f;

    load_stage(0, 0);
    cp_commit();

    #pragma unroll 1
    for (int kc = 0; kc < NC; kc++) {
        int s = kc & 1;
        if (kc + 1 < NC) load_stage((kc + 1) & 1, kc + 1);
        cp_commit();
        cp_wait<1>();
        __syncthreads();

        uint32_t stg = sb + (uint32_t)s * 16384u;
        #pragma unroll
        for (int k16 = 0; k16 < 2; k16++) {
            uint32_t a0[4][4], a1[4][4];
            #pragma unroll
            for (int mi = 0; mi < 4; mi++) {
                uint32_t off = (uint32_t)(raby[mi] + ((((k16 << 1) | hiA) ^ swa[mi]) << 4));
                ldm_x4(a0[mi], stg + off);
                ldm_x4(a1[mi], stg + 4096u + off);
            }
            uint32_t boff = (uint32_t)(rbby + ((((k16 << 1) | cbB) ^ swb) << 4));
            uint32_t bh[4];
            ldm_x4(bh, stg + 8192u + boff);
            #pragma unroll
            for (int mi = 0; mi < 4; mi++) {
                mma_bf16(acc[mi][0], a0[mi], &bh[0]);
                mma_bf16(acc[mi][1], a0[mi], &bh[2]);
                mma_bf16(acc[mi][0], a1[mi], &bh[0]);
                mma_bf16(acc[mi][1], a1[mi], &bh[2]);
            }
            uint32_t bl[4];
            ldm_x4(bl, stg + 12288u + boff);
            #pragma unroll
            for (int mi = 0; mi < 4; mi++) {
                mma_bf16(acc[mi][0], a0[mi], &bl[0]);
                mma_bf16(acc[mi][1], a0[mi], &bl[2]);
            }
        }
        __syncthreads();
    }

    // Epilogue: bias + relu + split -> bf16 hi/lo
    const int r0 = bm + (lane >> 2);
    const int c0 = bn + wn * 16 + (lane & 3) * 2;
    #pragma unroll
    for (int mi = 0; mi < 4; mi++) {
        #pragma unroll
        for (int nj = 0; nj < 2; nj++) {
            int c = c0 + nj * 8;
            float b0 = bias[c], b1 = bias[c + 1];
            float v00 = fmaxf(acc[mi][nj][0] + b0, 0.0f);
            float v01 = fmaxf(acc[mi][nj][1] + b1, 0.0f);
            float v10 = fmaxf(acc[mi][nj][2] + b0, 0.0f);
            float v11 = fmaxf(acc[mi][nj][3] + b1, 0.0f);
            bf16 h0, l0, h1, l1;
            split2(v00, h0, l0); split2(v01, h1, l1);
            size_t o0 = (size_t)(r0 + mi * 16) * HID + c;
            *(__nv_bfloat162*)(Chi + o0) = __halves2bfloat162(h0, h1);
            *(__nv_bfloat162*)(Clo + o0) = __halves2bfloat162(l0, l1);
            split2(v10, h0, l0); split2(v11, h1, l1);
            size_t o1 = (size_t)(r0 + mi * 16 + 8) * HID + c;
            *(__nv_bfloat162*)(Chi + o1) = __halves2bfloat162(h0, h1);
            *(__nv_bfloat162*)(Clo + o1) = __halves2bfloat162(l0, l1);
        }
    }
}

// ---------------------------------------------------------------------------
// Big HMMA GEMM: theta[1024,8192] = h2 @ Wout^T + bout (3-term split).
// Tile 128x128, BK=32, 256 threads (8 warps = 2m x 4n, warp 64m x 32n).
// All 4 tiles loaded once per chunk; cp.async double buffer; 64KB dyn smem.
// ---------------------------------------------------------------------------
__global__ void __launch_bounds__(256, 2) gemm_mma_kernel(
    const bf16* __restrict__ Ahi, const bf16* __restrict__ Alo,
    const bf16* __restrict__ Whi, const bf16* __restrict__ Wlo,
    const float* __restrict__ bias, float* __restrict__ C)
{
    extern __shared__ bf16 smd[];
    const int tid = threadIdx.x, lane = tid & 31, wrp = tid >> 5;
    const int wm = wrp >> 2, wn = wrp & 3;
    const int bm = blockIdx.y * 128, bn = blockIdx.x * 128;
    const uint32_t sb = smem_u32(smd);
    const int NC = HID / 32;  // 16

    auto load_stage = [&](int s, int kc) {
        uint32_t stg = sb + (uint32_t)s * 32768u;
        #pragma unroll
        for (int i = 0; i < 2; i++) {
            int idx = tid + i * 256;
            int r = idx >> 2, c = idx & 3;
            uint32_t dsw = (uint32_t)(r * 64 + ((c ^ ((r >> 1) & 3)) << 4));
            size_t asrc = (size_t)(bm + r) * HID + kc * 32 + c * 8;
            size_t wsrc = (size_t)(bn + r) * HID + kc * 32 + c * 8;
            cp16(stg + dsw,          Ahi + asrc);
            cp16(stg + 8192u + dsw,  Alo + asrc);
            cp16(stg + 16384u + dsw, Whi + wsrc);
            cp16(stg + 24576u + dsw, Wlo + wsrc);
        }
    };

    int raby[4], swa[4];
    #pragma unroll
    for (int mi = 0; mi < 4; mi++) {
        int r = wm * 64 + mi * 16 + (lane & 15);
        raby[mi] = r * 64;
        swa[mi] = (r >> 1) & 3;
    }
    const int hiA = lane >> 4;
    int rbby[2], swb[2];
    #pragma unroll
    for (int p = 0; p < 2; p++) {
        int n = wn * 32 + p * 16 + (((lane >> 3) >> 1) << 3) + (lane & 7);
        rbby[p] = n * 64;
        swb[p] = (n >> 1) & 3;
    }
    const int cbB = (lane >> 3) & 1;

    float acc[4][4][4];
    #pragma unroll
    for (int a = 0; a < 4; a++)
        #pragma unroll
        for (int bq = 0; bq < 4; bq++)
            #pragma unroll
            for (int q = 0; q < 4; q++) acc[a][bq][q] = 0.0f;

    load_stage(0, 0);
    cp_commit();

    #pragma unroll 1
    for (int kc = 0; kc < NC; kc++) {
        int s = kc & 1;
        if (kc + 1 < NC) load_stage((kc + 1) & 1, kc + 1);
        cp_commit();
        cp_wait<1>();
        __syncthreads();

        uint32_t stg = sb + (uint32_t)s * 32768u;
        #pragma unroll
        for (int k16 = 0; k16 < 2; k16++) {
            uint32_t a0[4][4], a1[4][4];
            #pragma unroll
            for (int mi = 0; mi < 4; mi++) {
                uint32_t off = (uint32_t)(raby[mi] + ((((k16 << 1) | hiA) ^ swa[mi]) << 4));
                ldm_x4(a0[mi], stg + off);
                ldm_x4(a1[mi], stg + 8192u + off);
            }
            #pragma unroll
            for (int p = 0; p < 2; p++) {
                uint32_t boff = (uint32_t)(rbby[p] + ((((k16 << 1) | cbB) ^ swb[p]) << 4));
                uint32_t bh[4];
                ldm_x4(bh, stg + 16384u + boff);
                #pragma unroll
                for (int mi = 0; mi < 4; mi++) {
                    mma_bf16(acc[mi][p * 2 + 0], a0[mi], &bh[0]);
                    mma_bf16(acc[mi][p * 2 + 1], a0[mi], &bh[2]);
                    mma_bf16(acc[mi][p * 2 + 0], a1[mi], &bh[0]);
                    mma_bf16(acc[mi][p * 2 + 1], a1[mi], &bh[2]);
                }
                uint32_t bl[4];
                ldm_x4(bl, stg + 24576u + boff);
                #pragma unroll
                for (int mi = 0; mi < 4; mi++) {
                    mma_bf16(acc[mi][p * 2 + 0], a0[mi], &bl[0]);
                    mma_bf16(acc[mi][p * 2 + 1], a0[mi], &bl[2]);
                }
            }
        }
        __syncthreads();
    }

    // Epilogue: bias + fp32 store
    const int r0 = bm + wm * 64 + (lane >> 2);
    const int cbase = bn + wn * 32 + (lane & 3) * 2;
    #pragma unroll
    for (int mi = 0; mi < 4; mi++) {
        #pragma unroll
        for (int nj = 0; nj < 4; nj++) {
            int col = cbase + nj * 8;
            float b0 = bias[col], b1 = bias[col + 1];
            float2 v0 = {acc[mi][nj][0] + b0, acc[mi][nj][1] + b1};
            float2 v1 = {acc[mi][nj][2] + b0, acc[mi][nj][3] + b1};
            *(float2*)(C + (size_t)(r0 + mi * 16) * NOUT + col)     = v0;
            *(float2*)(C + (size_t)(r0 + mi * 16 + 8) * NOUT + col) = v1;
        }
    }
}

// ---------------------------------------------------------------------------
// Fused log_px + forward chain. 16 lanes per batch, 2 batches/warp,
// 128 CTAs x 128 threads. Fast math + software-pipelined loads.
// ---------------------------------------------------------------------------
__global__ void __launch_bounds__(128) chain_kernel(
    const float* __restrict__ x, const float* __restrict__ theta,
    const float* __restrict__ ulpa, float* __restrict__ out)
{
    __shared__ float s_lpa[255 * 4];
    for (int d = threadIdx.x; d < 255; d += 128) {
        float u0 = ulpa[d * 4 + 0], u1 = ulpa[d * 4 + 1];
        float u2 = ulpa[d * 4 + 2], u3 = ulpa[d * 4 + 3];
        float m = fmaxf(fmaxf(u0, u1), fmaxf(u2, u3));
        float s = expf(u0 - m) + expf(u1 - m) + expf(u2 - m) + expf(u3 - m);
        float lse = m + logf(s);
        s_lpa[d * 4 + 0] = u0 - lse;
        s_lpa[d * 4 + 1] = u1 - lse;
        s_lpa[d * 4 + 2] = u2 - lse;
        s_lpa[d * 4 + 3] = u3 - lse;
    }
    __syncthreads();

    const int lane = threadIdx.x & 31;
    const int wid  = threadIdx.x >> 5;
    const int half = lane >> 4;
    const int l    = lane & 15;
    const int i    = l >> 2, j = l & 3;
    const int b    = (blockIdx.x * 4 + wid) * 2 + half;

    const unsigned FULL = 0xffffffffu;
    const float NL = -0.91893853320467274178f;  // -0.5*log(2*pi)

    const float* th = theta + (size_t)b * NOUT;
    const float* xb = x + (size_t)b * DIN;

    float carry;
    {   // d = 0
        float mu = __ldg(th + l), ls = __ldg(th + 16 + l);
        float xd = __ldg(xb);
        float sd = __expf(ls) + 0.01f;
        float z = __fdividef(xd - mu, sd);
        float lp = fmaf(-0.5f * z, z, NL) - __logf(sd);
        float v = lp + s_lpa[j];
        carry = __shfl_sync(FULL, v, half * 16 + j);
    }
    float mu = __ldg(th + 32 + l), ls = __ldg(th + 48 + l);
    float xd = __ldg(xb + 1);
    #pragma unroll 1
    for (int d = 1; d < 255; d++) {
        float nmu = __ldg(th + (d + 1) * 32 + l);
        float nls = __ldg(th + (d + 1) * 32 + 16 + l);
        float nxd = __ldg(xb + d + 1);
        float sd = __expf(ls) + 0.01f;
        float z = __fdividef(xd - mu, sd);
        float lp = fmaf(-0.5f * z, z, NL) - __logf(sd);
        float ci = __shfl_sync(FULL, carry, half * 16 + i);
        float tv = ci + lp + s_lpa[d * 4 + j];
        float m = fmaxf(tv, __shfl_xor_sync(FULL, tv, 4));
        m = fmaxf(m, __shfl_xor_sync(FULL, m, 8));
        float s = __expf(tv - m);
        s += __shfl_xor_sync(FULL, s, 4);
        s += __shfl_xor_sync(FULL, s, 8);
        carry = m + __logf(s);
        mu = nmu; ls = nls; xd = nxd;
    }
    {   // d = 255
        float sd = __expf(ls) + 0.01f;
        float z = __fdividef(xd - mu, sd);
        float lp = fmaf(-0.5f * z, z, NL) - __logf(sd);
        float ci = __shfl_sync(FULL, carry, half * 16 + i);
        float tv = (j == 0) ? (ci + lp) : -1e30f;
        float m = fmaxf(tv, __shfl_xor_sync(FULL, tv, 1));
        m = fmaxf(m, __shfl_xor_sync(FULL, m, 2));
        m = fmaxf(m, __shfl_xor_sync(FULL, m, 4));
        m = fmaxf(m, __shfl_xor_sync(FULL, m, 8));
        float s = __expf(tv - m);
        s += __shfl_xor_sync(FULL, s, 1);
        s += __shfl_xor_sync(FULL, s, 2);
        s += __shfl_xor_sync(FULL, s, 4);
        s += __shfl_xor_sync(FULL, s, 8);
        if (l == 0) out[b] = m + __logf(s);
    }
}

// ---------------------------------------------------------------------------
// kernel_launch
// ---------------------------------------------------------------------------
extern "C" void kernel_launch(void* const* d_in, const int* in_sizes, int n_in,
                              void* d_out, int out_size)
{
    const float* x    = (const float*)d_in[0];
    const float* W0   = (const float*)d_in[1];
    const float* b0   = (const float*)d_in[2];
    const float* W1   = (const float*)d_in[3];
    const float* b1   = (const float*)d_in[4];
    const float* W2   = (const float*)d_in[5];
    const float* b2   = (const float*)d_in[6];
    const float* Wout = (const float*)d_in[7];
    const float* bout = (const float*)d_in[8];
    const float* ulpa = (const float*)d_in[9];

    float* out   = (float*)d_out;
    float* theta = out + BATCH;

    bf16 *xhi, *xlo, *w0hi, *w0lo, *w1hi, *w1lo, *w2hi, *w2lo;
    bf16 *h0hi, *h0lo, *h1hi, *h1lo, *h2hi, *h2lo, *whi, *wlo;
    cudaGetSymbolAddress((void**)&xhi, g_xhi);   cudaGetSymbolAddress((void**)&xlo, g_xlo);
    cudaGetSymbolAddress((void**)&w0hi, g_w0hi); cudaGetSymbolAddress((void**)&w0lo, g_w0lo);
    cudaGetSymbolAddress((void**)&w1hi, g_w1hi); cudaGetSymbolAddress((void**)&w1lo, g_w1lo);
    cudaGetSymbolAddress((void**)&w2hi, g_w2hi); cudaGetSymbolAddress((void**)&w2lo, g_w2lo);
    cudaGetSymbolAddress((void**)&h0hi, g_h0hi); cudaGetSymbolAddress((void**)&h0lo, g_h0lo);
    cudaGetSymbolAddress((void**)&h1hi, g_h1hi); cudaGetSymbolAddress((void**)&h1lo, g_h1lo);
    cudaGetSymbolAddress((void**)&h2hi, g_h2hi); cudaGetSymbolAddress((void**)&h2lo, g_h2lo);
    cudaGetSymbolAddress((void**)&whi, g_whi);   cudaGetSymbolAddress((void**)&wlo, g_wlo);

    cudaFuncSetAttribute(gemm_mma_kernel,
                         cudaFuncAttributeMaxDynamicSharedMemorySize, 65536);

    split_wout_kernel<<<NOUT * HID / 4 / 256, 256>>>(Wout);
    prep_kernel<<<896, 256>>>(x, W0, W1, W2);

    layer_kernel<DIN><<<dim3(HID / 64, BATCH / 64), 128>>>(
        xhi, xlo, w0hi, w0lo, b0, h0hi, h0lo);
    layer_kernel<HID><<<dim3(HID / 64, BATCH / 64), 128>>>(
        h0hi, h0lo, w1hi, w1lo, b1, h1hi, h1lo);
    layer_kernel<HID><<<dim3(HID / 64, BATCH / 64), 128>>>(
        h1hi, h1lo, w2hi, w2lo, b2, h2hi, h2lo);

    gemm_mma_kernel<<<dim3(NOUT / 128, BATCH / 128), 256, 65536>>>(
        h2hi, h2lo, whi, wlo, bout, theta);

    chain_kernel<<<BATCH / 8, 128>>>(x, theta, ulpa, out);
}

// round 6
// speedup vs baseline: 2.4604x; 1.4654x over previous
#include <cuda_runtime.h>
#include <cuda_bf16.h>
#include <math.h>
#include <stdint.h>

#define BATCH 1024
#define DIN   256
#define HID   512
#define KOUT  32
#define NOUT  (DIN * KOUT)  // 8192

typedef __nv_bfloat16 bf16;

// Scratch (allocation-free rule -> __device__ globals)
__device__ bf16 g_xhi[BATCH * DIN],  g_xlo[BATCH * DIN];
__device__ bf16 g_w0hi[HID * DIN],   g_w0lo[HID * DIN];
__device__ bf16 g_w1hi[HID * HID],   g_w1lo[HID * HID];
__device__ bf16 g_w2hi[HID * HID],   g_w2lo[HID * HID];
__device__ bf16 g_h0hi[BATCH * HID], g_h0lo[BATCH * HID];
__device__ bf16 g_h1hi[BATCH * HID], g_h1lo[BATCH * HID];
__device__ bf16 g_h2hi[BATCH * HID], g_h2lo[BATCH * HID];
__device__ bf16 g_whi[NOUT * HID],   g_wlo[NOUT * HID];

// ---------------------------------------------------------------------------
// PTX helpers (sm_80-baseline: ldmatrix / mma.sync / cp.async — tcgen05 is
// rejected by this toolchain's compute_103 stage)
// ---------------------------------------------------------------------------
__device__ __forceinline__ uint32_t smem_u32(const void* p) {
    uint32_t a;
    asm("{ .reg .u64 t; cvta.to.shared.u64 t, %1; cvt.u32.u64 %0, t; }" : "=r"(a) : "l"(p));
    return a;
}
__device__ __forceinline__ void ldm_x4(uint32_t* r, uint32_t addr) {
    asm volatile("ldmatrix.sync.aligned.m8n8.x4.shared.b16 {%0,%1,%2,%3}, [%4];"
                 : "=r"(r[0]), "=r"(r[1]), "=r"(r[2]), "=r"(r[3]) : "r"(addr));
}
__device__ __forceinline__ void mma_bf16(float* d, const uint32_t* a, const uint32_t* b) {
    asm volatile("mma.sync.aligned.m16n8k16.row.col.f32.bf16.bf16.f32 "
                 "{%0,%1,%2,%3}, {%4,%5,%6,%7}, {%8,%9}, {%0,%1,%2,%3};"
                 : "+f"(d[0]), "+f"(d[1]), "+f"(d[2]), "+f"(d[3])
                 : "r"(a[0]), "r"(a[1]), "r"(a[2]), "r"(a[3]), "r"(b[0]), "r"(b[1]));
}
__device__ __forceinline__ void cp16(uint32_t dst, const void* src) {
    asm volatile("cp.async.cg.shared.global [%0], [%1], 16;" :: "r"(dst), "l"(src) : "memory");
}
__device__ __forceinline__ void cp_commit() {
    asm volatile("cp.async.commit_group;" ::: "memory");
}
template<int N> __device__ __forceinline__ void cp_wait() {
    asm volatile("cp.async.wait_group %0;" :: "n"(N) : "memory");
}
__device__ __forceinline__ void split2(float v, bf16& h, bf16& l) {
    h = __float2bfloat16(v);
    l = __float2bfloat16(v - __bfloat162float(h));
}
// min of (k % 255) over k in [a, a+32)
__device__ __forceinline__ int minmod255(int a) {
    return ((a + 31) / 255 > a / 255) ? 0 : (a % 255);
}

// ---------------------------------------------------------------------------
// Prep: split x, W0, W1, W2 into bf16 hi/lo with masks folded in.
// ---------------------------------------------------------------------------
__global__ void __launch_bounds__(256) prep_kernel(
    const float* __restrict__ x,  const float* __restrict__ W0,
    const float* __restrict__ W1, const float* __restrict__ W2)
{
    int t = blockIdx.x * 256 + threadIdx.x;
    const float* src; bf16 *hi, *lo;
    int mode, ksh, base;
    if (t < 65536)       { src = x;  hi = g_xhi;  lo = g_xlo;  mode = -1; ksh = 8; base = t * 4; }
    else if (t < 98304)  { src = W0; hi = g_w0hi; lo = g_w0lo; mode = 0;  ksh = 8; base = (t - 65536) * 4; }
    else if (t < 163840) { src = W1; hi = g_w1hi; lo = g_w1lo; mode = 1;  ksh = 9; base = (t - 98304) * 4; }
    else                 { src = W2; hi = g_w2hi; lo = g_w2lo; mode = 1;  ksh = 9; base = (t - 163840) * 4; }

    float4 v4 = *(const float4*)(src + base);
    float vv[4] = {v4.x, v4.y, v4.z, v4.w};
    int n = base >> ksh;
    int k0 = base & ((1 << ksh) - 1);
    int nd = n % 255;
    bf16 h[4], l[4];
    #pragma unroll
    for (int q = 0; q < 4; q++) {
        float v = vv[q];
        int k = k0 + q;
        if (mode == 0 && !(nd >= k)) v = 0.0f;
        if (mode == 1 && !(nd >= (k % 255))) v = 0.0f;
        split2(v, h[q], l[q]);
    }
    *(uint2*)(hi + base) = *(uint2*)h;
    *(uint2*)(lo + base) = *(uint2*)l;
}

// Wout split with output mask (MODE 2)
__global__ void __launch_bounds__(256) split_wout_kernel(const float* __restrict__ W)
{
    int idx = blockIdx.x * 256 + threadIdx.x;
    int base = idx * 4;
    int n = base >> 9, k0 = base & 511;
    int od = (n >> 5) - 1;
    float4 w4 = *(const float4*)(W + base);
    float wv[4] = {w4.x, w4.y, w4.z, w4.w};
    bf16 h[4], l[4];
    #pragma unroll
    for (int q = 0; q < 4; q++) {
        float v = (od >= ((k0 + q) % 255)) ? wv[q] : 0.0f;
        split2(v, h[q], l[q]);
    }
    *(uint2*)(g_whi + base) = *(uint2*)h;
    *(uint2*)(g_wlo + base) = *(uint2*)l;
}

// ---------------------------------------------------------------------------
// Small-layer HMMA kernel: C = relu(A @ W^T + b), split epilogue -> Chi/Clo.
// Tile 64x64, BK=32, 128 threads, 3-stage cp.async pipeline.
// Dead K-chunks (mask-zeroed W tiles) are skipped exactly.
// MODE 0: mask nd >= k (layer0). MODE 1: nd >= k%255 (hidden layers).
// ---------------------------------------------------------------------------
template<int K, int MODE>
__global__ void __launch_bounds__(128) layer_kernel(
    const bf16* __restrict__ Ahi, const bf16* __restrict__ Alo,
    const bf16* __restrict__ Whi, const bf16* __restrict__ Wlo,
    const float* __restrict__ bias,
    bf16* __restrict__ Chi, bf16* __restrict__ Clo)
{
    constexpr int NC = K / 32;
    constexpr int S = 3;
    extern __shared__ bf16 smL[];      // S stages x 16KB
    const int tid = threadIdx.x, lane = tid & 31, wn = tid >> 5;
    const int bm = blockIdx.y * 64;
    const int bn = ((int)gridDim.x - 1 - (int)blockIdx.x) * 64;
    const uint32_t sb = smem_u32(smL);

    // active-chunk list (uniform across CTA)
    int md = 0;
    for (int r = 0; r < 64; r++) { int v = (bn + r) % 255; md = v > md ? v : md; }
    int act[NC]; int na = 0;
    #pragma unroll
    for (int kc = 0; kc < NC; kc++) {
        int mm = (MODE == 0) ? (32 * kc) : minmod255(32 * kc);
        if (md >= mm) act[na++] = kc;
    }

    auto load_stage = [&](int s, int kc) {
        uint32_t stg = sb + (uint32_t)s * 16384u;
        #pragma unroll
        for (int i = 0; i < 2; i++) {
            int idx = tid + i * 128;
            int r = idx >> 2, c = idx & 3;
            uint32_t dsw = (uint32_t)(r * 64 + ((c ^ ((r >> 1) & 3)) << 4));
            size_t asrc = (size_t)(bm + r) * K + kc * 32 + c * 8;
            size_t wsrc = (size_t)(bn + r) * K + kc * 32 + c * 8;
            cp16(stg + dsw,          Ahi + asrc);
            cp16(stg + 4096u + dsw,  Alo + asrc);
            cp16(stg + 8192u + dsw,  Whi + wsrc);
            cp16(stg + 12288u + dsw, Wlo + wsrc);
        }
    };

    int raby[4], swa[4];
    #pragma unroll
    for (int mi = 0; mi < 4; mi++) {
        int r = mi * 16 + (lane & 15);
        raby[mi] = r * 64;
        swa[mi] = (r >> 1) & 3;
    }
    const int hiA = lane >> 4;
    const int nloc = wn * 16 + (((lane >> 3) >> 1) << 3) + (lane & 7);
    const int rbby = nloc * 64, swb = (nloc >> 1) & 3, cbB = (lane >> 3) & 1;

    float acc[4][2][4];
    #pragma unroll
    for (int a = 0; a < 4; a++)
        #pragma unroll
        for (int bq = 0; bq < 2; bq++)
            #pragma unroll
            for (int q = 0; q < 4; q++) acc[a][bq][q] = 0.0f;

    #pragma unroll
    for (int s = 0; s < S - 1; s++) { if (s < na) load_stage(s, act[s]); cp_commit(); }

    #pragma unroll 1
    for (int ii = 0; ii < na; ii++) {
        cp_wait<S - 2>();
        __syncthreads();
        int ld = ii + S - 1;
        if (ld < na) load_stage(ld % S, act[ld]);
        cp_commit();

        uint32_t stg = sb + (uint32_t)(ii % S) * 16384u;
        #pragma unroll
        for (int k16 = 0; k16 < 2; k16++) {
            uint32_t a0[4][4], a1[4][4];
            #pragma unroll
            for (int mi = 0; mi < 4; mi++) {
                uint32_t off = (uint32_t)(raby[mi] + ((((k16 << 1) | hiA) ^ swa[mi]) << 4));
                ldm_x4(a0[mi], stg + off);
                ldm_x4(a1[mi], stg + 4096u + off);
            }
            uint32_t boff = (uint32_t)(rbby + ((((k16 << 1) | cbB) ^ swb) << 4));
            uint32_t bh[4];
            ldm_x4(bh, stg + 8192u + boff);
            #pragma unroll
            for (int mi = 0; mi < 4; mi++) {
                mma_bf16(acc[mi][0], a0[mi], &bh[0]);
                mma_bf16(acc[mi][1], a0[mi], &bh[2]);
                mma_bf16(acc[mi][0], a1[mi], &bh[0]);
                mma_bf16(acc[mi][1], a1[mi], &bh[2]);
            }
            uint32_t bl[4];
            ldm_x4(bl, stg + 12288u + boff);
            #pragma unroll
            for (int mi = 0; mi < 4; mi++) {
                mma_bf16(acc[mi][0], a0[mi], &bl[0]);
                mma_bf16(acc[mi][1], a0[mi], &bl[2]);
            }
        }
    }
    cp_wait<0>();

    // Epilogue: bias + relu + split -> bf16 hi/lo
    const int r0 = bm + (lane >> 2);
    const int c0 = bn + wn * 16 + (lane & 3) * 2;
    #pragma unroll
    for (int mi = 0; mi < 4; mi++) {
        #pragma unroll
        for (int nj = 0; nj < 2; nj++) {
            int c = c0 + nj * 8;
            float b0 = bias[c], b1 = bias[c + 1];
            float v00 = fmaxf(acc[mi][nj][0] + b0, 0.0f);
            float v01 = fmaxf(acc[mi][nj][1] + b1, 0.0f);
            float v10 = fmaxf(acc[mi][nj][2] + b0, 0.0f);
            float v11 = fmaxf(acc[mi][nj][3] + b1, 0.0f);
            bf16 h0, l0, h1, l1;
            split2(v00, h0, l0); split2(v01, h1, l1);
            size_t o0 = (size_t)(r0 + mi * 16) * HID + c;
            *(__nv_bfloat162*)(Chi + o0) = __halves2bfloat162(h0, h1);
            *(__nv_bfloat162*)(Clo + o0) = __halves2bfloat162(l0, l1);
            split2(v10, h0, l0); split2(v11, h1, l1);
            size_t o1 = (size_t)(r0 + mi * 16 + 8) * HID + c;
            *(__nv_bfloat162*)(Chi + o1) = __halves2bfloat162(h0, h1);
            *(__nv_bfloat162*)(Clo + o1) = __halves2bfloat162(l0, l1);
        }
    }
}

// ---------------------------------------------------------------------------
// Big HMMA GEMM: theta[1024,8192] = h2 @ Wout^T + bout (3-term split).
// Tile 128x128, BK=32, 256 threads, 3-stage pipeline, chunk-skip by mask,
// heavy tiles first (reversed bid).
// ---------------------------------------------------------------------------
__global__ void __launch_bounds__(256) gemm_mma_kernel(
    const bf16* __restrict__ Ahi, const bf16* __restrict__ Alo,
    const bf16* __restrict__ Whi, const bf16* __restrict__ Wlo,
    const float* __restrict__ bias, float* __restrict__ C)
{
    constexpr int NC = HID / 32;   // 16
    constexpr int S = 3;
    extern __shared__ bf16 smd[];
    const int tid = threadIdx.x, lane = tid & 31, wrp = tid >> 5;
    const int wm = wrp >> 2, wn = wrp & 3;
    const int bm = blockIdx.y * 128;
    const int bn = ((int)gridDim.x - 1 - (int)blockIdx.x) * 128;
    const uint32_t sb = smem_u32(smd);

    // active-chunk list: W nonzero iff min(k%255) <= bn/32 + 2
    const int T = (bn >> 5) + 2;
    int act[NC]; int na = 0;
    #pragma unroll
    for (int kc = 0; kc < NC; kc++)
        if (minmod255(32 * kc) <= T) act[na++] = kc;

    auto load_stage = [&](int s, int kc) {
        uint32_t stg = sb + (uint32_t)s * 32768u;
        #pragma unroll
        for (int i = 0; i < 2; i++) {
            int idx = tid + i * 256;
            int r = idx >> 2, c = idx & 3;
            uint32_t dsw = (uint32_t)(r * 64 + ((c ^ ((r >> 1) & 3)) << 4));
            size_t asrc = (size_t)(bm + r) * HID + kc * 32 + c * 8;
            size_t wsrc = (size_t)(bn + r) * HID + kc * 32 + c * 8;
            cp16(stg + dsw,          Ahi + asrc);
            cp16(stg + 8192u + dsw,  Alo + asrc);
            cp16(stg + 16384u + dsw, Whi + wsrc);
            cp16(stg + 24576u + dsw, Wlo + wsrc);
        }
    };

    int raby[4], swa[4];
    #pragma unroll
    for (int mi = 0; mi < 4; mi++) {
        int r = wm * 64 + mi * 16 + (lane & 15);
        raby[mi] = r * 64;
        swa[mi] = (r >> 1) & 3;
    }
    const int hiA = lane >> 4;
    int rbby[2], swb[2];
    #pragma unroll
    for (int p = 0; p < 2; p++) {
        int n = wn * 32 + p * 16 + (((lane >> 3) >> 1) << 3) + (lane & 7);
        rbby[p] = n * 64;
        swb[p] = (n >> 1) & 3;
    }
    const int cbB = (lane >> 3) & 1;

    float acc[4][4][4];
    #pragma unroll
    for (int a = 0; a < 4; a++)
        #pragma unroll
        for (int bq = 0; bq < 4; bq++)
            #pragma unroll
            for (int q = 0; q < 4; q++) acc[a][bq][q] = 0.0f;

    #pragma unroll
    for (int s = 0; s < S - 1; s++) { if (s < na) load_stage(s, act[s]); cp_commit(); }

    #pragma unroll 1
    for (int ii = 0; ii < na; ii++) {
        cp_wait<S - 2>();
        __syncthreads();
        int ld = ii + S - 1;
        if (ld < na) load_stage(ld % S, act[ld]);
        cp_commit();

        uint32_t stg = sb + (uint32_t)(ii % S) * 32768u;
        #pragma unroll
        for (int k16 = 0; k16 < 2; k16++) {
            uint32_t a0[4][4], a1[4][4];
            #pragma unroll
            for (int mi = 0; mi < 4; mi++) {
                uint32_t off = (uint32_t)(raby[mi] + ((((k16 << 1) | hiA) ^ swa[mi]) << 4));
                ldm_x4(a0[mi], stg + off);
                ldm_x4(a1[mi], stg + 8192u + off);
            }
            #pragma unroll
            for (int p = 0; p < 2; p++) {
                uint32_t boff = (uint32_t)(rbby[p] + ((((k16 << 1) | cbB) ^ swb[p]) << 4));
                uint32_t bh[4];
                ldm_x4(bh, stg + 16384u + boff);
                #pragma unroll
                for (int mi = 0; mi < 4; mi++) {
                    mma_bf16(acc[mi][p * 2 + 0], a0[mi], &bh[0]);
                    mma_bf16(acc[mi][p * 2 + 1], a0[mi], &bh[2]);
                    mma_bf16(acc[mi][p * 2 + 0], a1[mi], &bh[0]);
                    mma_bf16(acc[mi][p * 2 + 1], a1[mi], &bh[2]);
                }
                uint32_t bl[4];
                ldm_x4(bl, stg + 24576u + boff);
                #pragma unroll
                for (int mi = 0; mi < 4; mi++) {
                    mma_bf16(acc[mi][p * 2 + 0], a0[mi], &bl[0]);
                    mma_bf16(acc[mi][p * 2 + 1], a0[mi], &bl[2]);
                }
            }
        }
    }
    cp_wait<0>();

    // Epilogue: bias + fp32 store
    const int r0 = bm + wm * 64 + (lane >> 2);
    const int cbase = bn + wn * 32 + (lane & 3) * 2;
    #pragma unroll
    for (int mi = 0; mi < 4; mi++) {
        #pragma unroll
        for (int nj = 0; nj < 4; nj++) {
            int col = cbase + nj * 8;
            float b0 = bias[col], b1 = bias[col + 1];
            float2 v0 = {acc[mi][nj][0] + b0, acc[mi][nj][1] + b1};
            float2 v1 = {acc[mi][nj][2] + b0, acc[mi][nj][3] + b1};
            *(float2*)(C + (size_t)(r0 + mi * 16) * NOUT + col)     = v0;
            *(float2*)(C + (size_t)(r0 + mi * 16 + 8) * NOUT + col) = v1;
        }
    }
}

// ---------------------------------------------------------------------------
// Fused log_px + forward chain. 16 lanes/batch, 2 batches/warp.
// ---------------------------------------------------------------------------
__global__ void __launch_bounds__(128) chain_kernel(
    const float* __restrict__ x, const float* __restrict__ theta,
    const float* __restrict__ ulpa, float* __restrict__ out)
{
    __shared__ float s_lpa[255 * 4];
    for (int d = threadIdx.x; d < 255; d += 128) {
        float u0 = ulpa[d * 4 + 0], u1 = ulpa[d * 4 + 1];
        float u2 = ulpa[d * 4 + 2], u3 = ulpa[d * 4 + 3];
        float m = fmaxf(fmaxf(u0, u1), fmaxf(u2, u3));
        float s = expf(u0 - m) + expf(u1 - m) + expf(u2 - m) + expf(u3 - m);
        float lse = m + logf(s);
        s_lpa[d * 4 + 0] = u0 - lse;
        s_lpa[d * 4 + 1] = u1 - lse;
        s_lpa[d * 4 + 2] = u2 - lse;
        s_lpa[d * 4 + 3] = u3 - lse;
    }
    __syncthreads();

    const int lane = threadIdx.x & 31;
    const int wid  = threadIdx.x >> 5;
    const int half = lane >> 4;
    const int l    = lane & 15;
    const int i    = l >> 2, j = l & 3;
    const int b    = (blockIdx.x * 4 + wid) * 2 + half;

    const unsigned FULL = 0xffffffffu;
    const float NL = -0.91893853320467274178f;  // -0.5*log(2*pi)

    const float* th = theta + (size_t)b * NOUT;
    const float* xb = x + (size_t)b * DIN;

    float carry;
    {   // d = 0
        float mu = __ldg(th + l), ls = __ldg(th + 16 + l);
        float xd = __ldg(xb);
        float sd = __expf(ls) + 0.01f;
        float z = __fdividef(xd - mu, sd);
        float lp = fmaf(-0.5f * z, z, NL) - __logf(sd);
        float v = lp + s_lpa[j];
        carry = __shfl_sync(FULL, v, half * 16 + j);
    }
    float mu = __ldg(th + 32 + l), ls = __ldg(th + 48 + l);
    float xd = __ldg(xb + 1);
    #pragma unroll 1
    for (int d = 1; d < 255; d++) {
        float nmu = __ldg(th + (d + 1) * 32 + l);
        float nls = __ldg(th + (d + 1) * 32 + 16 + l);
        float nxd = __ldg(xb + d + 1);
        float sd = __expf(ls) + 0.01f;
        float z = __fdividef(xd - mu, sd);
        float lp = fmaf(-0.5f * z, z, NL) - __logf(sd);
        float ci = __shfl_sync(FULL, carry, half * 16 + i);
        float tv = ci + lp + s_lpa[d * 4 + j];
        float m = fmaxf(tv, __shfl_xor_sync(FULL, tv, 4));
        m = fmaxf(m, __shfl_xor_sync(FULL, m, 8));
        float s = __expf(tv - m);
        s += __shfl_xor_sync(FULL, s, 4);
        s += __shfl_xor_sync(FULL, s, 8);
        carry = m + __logf(s);
        mu = nmu; ls = nls; xd = nxd;
    }
    {   // d = 255
        float sd = __expf(ls) + 0.01f;
        float z = __fdividef(xd - mu, sd);
        float lp = fmaf(-0.5f * z, z, NL) - __logf(sd);
        float ci = __shfl_sync(FULL, carry, half * 16 + i);
        float tv = (j == 0) ? (ci + lp) : -1e30f;
        float m = fmaxf(tv, __shfl_xor_sync(FULL, tv, 1));
        m = fmaxf(m, __shfl_xor_sync(FULL, m, 2));
        m = fmaxf(m, __shfl_xor_sync(FULL, m, 4));
        m = fmaxf(m, __shfl_xor_sync(FULL, m, 8));
        float s = __expf(tv - m);
        s += __shfl_xor_sync(FULL, s, 1);
        s += __shfl_xor_sync(FULL, s, 2);
        s += __shfl_xor_sync(FULL, s, 4);
        s += __shfl_xor_sync(FULL, s, 8);
        if (l == 0) out[b] = m + __logf(s);
    }
}

// ---------------------------------------------------------------------------
// kernel_launch
// ---------------------------------------------------------------------------
extern "C" void kernel_launch(void* const* d_in, const int* in_sizes, int n_in,
                              void* d_out, int out_size)
{
    const float* x    = (const float*)d_in[0];
    const float* W0   = (const float*)d_in[1];
    const float* b0   = (const float*)d_in[2];
    const float* W1   = (const float*)d_in[3];
    const float* b1   = (const float*)d_in[4];
    const float* W2   = (const float*)d_in[5];
    const float* b2   = (const float*)d_in[6];
    const float* Wout = (const float*)d_in[7];
    const float* bout = (const float*)d_in[8];
    const float* ulpa = (const float*)d_in[9];

    float* out   = (float*)d_out;
    float* theta = out + BATCH;

    bf16 *xhi, *xlo, *w0hi, *w0lo, *w1hi, *w1lo, *w2hi, *w2lo;
    bf16 *h0hi, *h0lo, *h1hi, *h1lo, *h2hi, *h2lo, *whi, *wlo;
    cudaGetSymbolAddress((void**)&xhi, g_xhi);   cudaGetSymbolAddress((void**)&xlo, g_xlo);
    cudaGetSymbolAddress((void**)&w0hi, g_w0hi); cudaGetSymbolAddress((void**)&w0lo, g_w0lo);
    cudaGetSymbolAddress((void**)&w1hi, g_w1hi); cudaGetSymbolAddress((void**)&w1lo, g_w1lo);
    cudaGetSymbolAddress((void**)&w2hi, g_w2hi); cudaGetSymbolAddress((void**)&w2lo, g_w2lo);
    cudaGetSymbolAddress((void**)&h0hi, g_h0hi); cudaGetSymbolAddress((void**)&h0lo, g_h0lo);
    cudaGetSymbolAddress((void**)&h1hi, g_h1hi); cudaGetSymbolAddress((void**)&h1lo, g_h1lo);
    cudaGetSymbolAddress((void**)&h2hi, g_h2hi); cudaGetSymbolAddress((void**)&h2lo, g_h2lo);
    cudaGetSymbolAddress((void**)&whi, g_whi);   cudaGetSymbolAddress((void**)&wlo, g_wlo);

    cudaFuncSetAttribute(gemm_mma_kernel,
                         cudaFuncAttributeMaxDynamicSharedMemorySize, 98304);
    cudaFuncSetAttribute(layer_kernel<DIN, 0>,
                         cudaFuncAttributeMaxDynamicSharedMemorySize, 49152);
    cudaFuncSetAttribute(layer_kernel<HID, 1>,
                         cudaFuncAttributeMaxDynamicSharedMemorySize, 49152);

    split_wout_kernel<<<NOUT * HID / 4 / 256, 256>>>(Wout);
    prep_kernel<<<896, 256>>>(x, W0, W1, W2);

    layer_kernel<DIN, 0><<<dim3(HID / 64, BATCH / 64), 128, 49152>>>(
        xhi, xlo, w0hi, w0lo, b0, h0hi, h0lo);
    layer_kernel<HID, 1><<<dim3(HID / 64, BATCH / 64), 128, 49152>>>(
        h0hi, h0lo, w1hi, w1lo, b1, h1hi, h1lo);
    layer_kernel<HID, 1><<<dim3(HID / 64, BATCH / 64), 128, 49152>>>(
        h1hi, h1lo, w2hi, w2lo, b2, h2hi, h2lo);

    gemm_mma_kernel<<<dim3(NOUT / 128, BATCH / 128), 256, 98304>>>(
        h2hi, h2lo, whi, wlo, bout, theta);

    chain_kernel<<<BATCH / 8, 128>>>(x, theta, ulpa, out);
}

// round 7
// speedup vs baseline: 2.5712x; 1.0451x over previous
#include <cuda_runtime.h>
#include <cuda_bf16.h>
#include <math.h>
#include <stdint.h>

#define BATCH 1024
#define DIN   256
#define HID   512
#define KOUT  32
#define NOUT  (DIN * KOUT)  // 8192

typedef __nv_bfloat16 bf16;

// Scratch (allocation-free rule -> __device__ globals)
__device__ bf16 g_xhi[BATCH * DIN],  g_xlo[BATCH * DIN];
__device__ bf16 g_w0hi[HID * DIN],   g_w0lo[HID * DIN];
__device__ bf16 g_w1hi[HID * HID],   g_w1lo[HID * HID];
__device__ bf16 g_w2hi[HID * HID],   g_w2lo[HID * HID];
__device__ bf16 g_h0hi[BATCH * HID], g_h0lo[BATCH * HID];
__device__ bf16 g_h1hi[BATCH * HID], g_h1lo[BATCH * HID];
__device__ bf16 g_h2hi[BATCH * HID], g_h2lo[BATCH * HID];
__device__ bf16 g_whi[NOUT * HID],   g_wlo[NOUT * HID];

// ---------------------------------------------------------------------------
// PTX helpers (sm_80-baseline: ldmatrix / mma.sync / cp.async — tcgen05 is
// rejected by this toolchain's compute_103 stage)
// ---------------------------------------------------------------------------
__device__ __forceinline__ uint32_t smem_u32(const void* p) {
    uint32_t a;
    asm("{ .reg .u64 t; cvta.to.shared.u64 t, %1; cvt.u32.u64 %0, t; }" : "=r"(a) : "l"(p));
    return a;
}
__device__ __forceinline__ void ldm_x4(uint32_t* r, uint32_t addr) {
    asm volatile("ldmatrix.sync.aligned.m8n8.x4.shared.b16 {%0,%1,%2,%3}, [%4];"
                 : "=r"(r[0]), "=r"(r[1]), "=r"(r[2]), "=r"(r[3]) : "r"(addr));
}
__device__ __forceinline__ void mma_bf16(float* d, const uint32_t* a, const uint32_t* b) {
    asm volatile("mma.sync.aligned.m16n8k16.row.col.f32.bf16.bf16.f32 "
                 "{%0,%1,%2,%3}, {%4,%5,%6,%7}, {%8,%9}, {%0,%1,%2,%3};"
                 : "+f"(d[0]), "+f"(d[1]), "+f"(d[2]), "+f"(d[3])
                 : "r"(a[0]), "r"(a[1]), "r"(a[2]), "r"(a[3]), "r"(b[0]), "r"(b[1]));
}
__device__ __forceinline__ void cp16(uint32_t dst, const void* src) {
    asm volatile("cp.async.cg.shared.global [%0], [%1], 16;" :: "r"(dst), "l"(src) : "memory");
}
__device__ __forceinline__ void cp_commit() {
    asm volatile("cp.async.commit_group;" ::: "memory");
}
template<int N> __device__ __forceinline__ void cp_wait() {
    asm volatile("cp.async.wait_group %0;" :: "n"(N) : "memory");
}
__device__ __forceinline__ void split2(float v, bf16& h, bf16& l) {
    h = __float2bfloat16(v);
    l = __float2bfloat16(v - __bfloat162float(h));
}
// min of (k % 255) over k in [a, a+32)
__device__ __forceinline__ int minmod255(int a) {
    return ((a + 31) / 255 > a / 255) ? 0 : (a % 255);
}

// ---------------------------------------------------------------------------
// Prep: split x, W0, W1, W2 into bf16 hi/lo with masks folded in.
// ---------------------------------------------------------------------------
__global__ void __launch_bounds__(256) prep_kernel(
    const float* __restrict__ x,  const float* __restrict__ W0,
    const float* __restrict__ W1, const float* __restrict__ W2)
{
    int t = blockIdx.x * 256 + threadIdx.x;
    const float* src; bf16 *hi, *lo;
    int mode, ksh, base;
    if (t < 65536)       { src = x;  hi = g_xhi;  lo = g_xlo;  mode = -1; ksh = 8; base = t * 4; }
    else if (t < 98304)  { src = W0; hi = g_w0hi; lo = g_w0lo; mode = 0;  ksh = 8; base = (t - 65536) * 4; }
    else if (t < 163840) { src = W1; hi = g_w1hi; lo = g_w1lo; mode = 1;  ksh = 9; base = (t - 98304) * 4; }
    else                 { src = W2; hi = g_w2hi; lo = g_w2lo; mode = 1;  ksh = 9; base = (t - 163840) * 4; }

    float4 v4 = *(const float4*)(src + base);
    float vv[4] = {v4.x, v4.y, v4.z, v4.w};
    int n = base >> ksh;
    int k0 = base & ((1 << ksh) - 1);
    int nd = n % 255;
    bf16 h[4], l[4];
    #pragma unroll
    for (int q = 0; q < 4; q++) {
        float v = vv[q];
        int k = k0 + q;
        if (mode == 0 && !(nd >= k)) v = 0.0f;
        if (mode == 1 && !(nd >= (k % 255))) v = 0.0f;
        split2(v, h[q], l[q]);
    }
    *(uint2*)(hi + base) = *(uint2*)h;
    *(uint2*)(lo + base) = *(uint2*)l;
}

// Wout split with output mask (MODE 2)
__global__ void __launch_bounds__(256) split_wout_kernel(const float* __restrict__ W)
{
    int idx = blockIdx.x * 256 + threadIdx.x;
    int base = idx * 4;
    int n = base >> 9, k0 = base & 511;
    int od = (n >> 5) - 1;
    float4 w4 = *(const float4*)(W + base);
    float wv[4] = {w4.x, w4.y, w4.z, w4.w};
    bf16 h[4], l[4];
    #pragma unroll
    for (int q = 0; q < 4; q++) {
        float v = (od >= ((k0 + q) % 255)) ? wv[q] : 0.0f;
        split2(v, h[q], l[q]);
    }
    *(uint2*)(g_whi + base) = *(uint2*)h;
    *(uint2*)(g_wlo + base) = *(uint2*)l;
}

// ---------------------------------------------------------------------------
// Small-layer HMMA kernel: C = relu(A @ W^T + b), split epilogue -> Chi/Clo.
// Tile 32m x 64n, BK=32, 128 threads (4 warps all in n; warp = 32m x 16n).
// grid = (N/64, M/32) = 256 CTAs -> all SMs busy + multiple CTAs/SM.
// 3-stage cp.async; dead K-chunks skipped exactly.
// ---------------------------------------------------------------------------
template<int K, int MODE>
__global__ void __launch_bounds__(128) layer_kernel(
    const bf16* __restrict__ Ahi, const bf16* __restrict__ Alo,
    const bf16* __restrict__ Whi, const bf16* __restrict__ Wlo,
    const float* __restrict__ bias,
    bf16* __restrict__ Chi, bf16* __restrict__ Clo)
{
    constexpr int NC = K / 32;
    constexpr int S = 3;
    constexpr uint32_t STG = 12288;  // 12KB per stage
    extern __shared__ bf16 smL[];
    const int tid = threadIdx.x, lane = tid & 31, wn = tid >> 5;
    const int bm = blockIdx.y * 32;
    const int bn = ((int)gridDim.x - 1 - (int)blockIdx.x) * 64;
    const uint32_t sb = smem_u32(smL);

    // max of (bn+r)%255 over the 64 N-rows (analytic)
    const int md = (bn / 255 == (bn + 63) / 255) ? ((bn + 63) % 255) : 254;

    int act[NC]; int na = 0;
    #pragma unroll
    for (int kc = 0; kc < NC; kc++) {
        int mm = (MODE == 0) ? (32 * kc) : minmod255(32 * kc);
        if (md >= mm) act[na++] = kc;
    }

    auto load_stage = [&](int s, int kc) {
        uint32_t stg = sb + (uint32_t)s * STG;
        {   // A tiles: 32 rows x 32 cols (64B/row), hi+lo
            int r = tid >> 2, c = tid & 3;
            uint32_t dsw = (uint32_t)(r * 64 + ((c ^ ((r >> 1) & 3)) << 4));
            size_t asrc = (size_t)(bm + r) * K + kc * 32 + c * 8;
            cp16(stg + dsw,         Ahi + asrc);
            cp16(stg + 2048u + dsw, Alo + asrc);
        }
        #pragma unroll
        for (int i = 0; i < 2; i++) {  // W tiles: 64 rows, hi+lo
            int idx = tid + i * 128;
            int r = idx >> 2, c = idx & 3;
            uint32_t dsw = (uint32_t)(r * 64 + ((c ^ ((r >> 1) & 3)) << 4));
            size_t wsrc = (size_t)(bn + r) * K + kc * 32 + c * 8;
            cp16(stg + 4096u + dsw, Whi + wsrc);
            cp16(stg + 8192u + dsw, Wlo + wsrc);
        }
    };

    int raby[2], swa[2];
    #pragma unroll
    for (int mi = 0; mi < 2; mi++) {
        int r = mi * 16 + (lane & 15);
        raby[mi] = r * 64;
        swa[mi] = (r >> 1) & 3;
    }
    const int hiA = lane >> 4;
    const int nloc = wn * 16 + (((lane >> 3) >> 1) << 3) + (lane & 7);
    const int rbby = nloc * 64, swb = (nloc >> 1) & 3, cbB = (lane >> 3) & 1;

    float acc[2][2][4];
    #pragma unroll
    for (int a = 0; a < 2; a++)
        #pragma unroll
        for (int bq = 0; bq < 2; bq++)
            #pragma unroll
            for (int q = 0; q < 4; q++) acc[a][bq][q] = 0.0f;

    #pragma unroll
    for (int s = 0; s < S - 1; s++) { if (s < na) load_stage(s, act[s]); cp_commit(); }

    #pragma unroll 1
    for (int ii = 0; ii < na; ii++) {
        cp_wait<S - 2>();
        __syncthreads();
        int ld = ii + S - 1;
        if (ld < na) load_stage(ld % S, act[ld]);
        cp_commit();

        uint32_t stg = sb + (uint32_t)(ii % S) * STG;
        #pragma unroll
        for (int k16 = 0; k16 < 2; k16++) {
            uint32_t a0[2][4], a1[2][4];
            #pragma unroll
            for (int mi = 0; mi < 2; mi++) {
                uint32_t off = (uint32_t)(raby[mi] + ((((k16 << 1) | hiA) ^ swa[mi]) << 4));
                ldm_x4(a0[mi], stg + off);
                ldm_x4(a1[mi], stg + 2048u + off);
            }
            uint32_t boff = (uint32_t)(rbby + ((((k16 << 1) | cbB) ^ swb) << 4));
            uint32_t bh[4];
            ldm_x4(bh, stg + 4096u + boff);
            #pragma unroll
            for (int mi = 0; mi < 2; mi++) {
                mma_bf16(acc[mi][0], a0[mi], &bh[0]);
                mma_bf16(acc[mi][1], a0[mi], &bh[2]);
                mma_bf16(acc[mi][0], a1[mi], &bh[0]);
                mma_bf16(acc[mi][1], a1[mi], &bh[2]);
            }
            uint32_t bl[4];
            ldm_x4(bl, stg + 8192u + boff);
            #pragma unroll
            for (int mi = 0; mi < 2; mi++) {
                mma_bf16(acc[mi][0], a0[mi], &bl[0]);
                mma_bf16(acc[mi][1], a0[mi], &bl[2]);
            }
        }
    }
    cp_wait<0>();

    // Epilogue: bias + relu + split -> bf16 hi/lo
    const int r0 = bm + (lane >> 2);
    const int c0 = bn + wn * 16 + (lane & 3) * 2;
    #pragma unroll
    for (int mi = 0; mi < 2; mi++) {
        #pragma unroll
        for (int nj = 0; nj < 2; nj++) {
            int c = c0 + nj * 8;
            float b0 = bias[c], b1 = bias[c + 1];
            float v00 = fmaxf(acc[mi][nj][0] + b0, 0.0f);
            float v01 = fmaxf(acc[mi][nj][1] + b1, 0.0f);
            float v10 = fmaxf(acc[mi][nj][2] + b0, 0.0f);
            float v11 = fmaxf(acc[mi][nj][3] + b1, 0.0f);
            bf16 h0, l0, h1, l1;
            split2(v00, h0, l0); split2(v01, h1, l1);
            size_t o0 = (size_t)(r0 + mi * 16) * HID + c;
            *(__nv_bfloat162*)(Chi + o0) = __halves2bfloat162(h0, h1);
            *(__nv_bfloat162*)(Clo + o0) = __halves2bfloat162(l0, l1);
            split2(v10, h0, l0); split2(v11, h1, l1);
            size_t o1 = (size_t)(r0 + mi * 16 + 8) * HID + c;
            *(__nv_bfloat162*)(Chi + o1) = __halves2bfloat162(h0, h1);
            *(__nv_bfloat162*)(Clo + o1) = __halves2bfloat162(l0, l1);
        }
    }
}

// ---------------------------------------------------------------------------
// Big HMMA GEMM: theta[1024,8192] = h2 @ Wout^T + bout (3-term split).
// Tile 128x128, BK=32, 256 threads, 3-stage pipeline, chunk-skip by mask,
// heavy tiles first (reversed bid). (Unchanged from R6 — it worked.)
// ---------------------------------------------------------------------------
__global__ void __launch_bounds__(256) gemm_mma_kernel(
    const bf16* __restrict__ Ahi, const bf16* __restrict__ Alo,
    const bf16* __restrict__ Whi, const bf16* __restrict__ Wlo,
    const float* __restrict__ bias, float* __restrict__ C)
{
    constexpr int NC = HID / 32;   // 16
    constexpr int S = 3;
    extern __shared__ bf16 smd[];
    const int tid = threadIdx.x, lane = tid & 31, wrp = tid >> 5;
    const int wm = wrp >> 2, wn = wrp & 3;
    const int bm = blockIdx.y * 128;
    const int bn = ((int)gridDim.x - 1 - (int)blockIdx.x) * 128;
    const uint32_t sb = smem_u32(smd);

    const int T = (bn >> 5) + 2;
    int act[NC]; int na = 0;
    #pragma unroll
    for (int kc = 0; kc < NC; kc++)
        if (minmod255(32 * kc) <= T) act[na++] = kc;

    auto load_stage = [&](int s, int kc) {
        uint32_t stg = sb + (uint32_t)s * 32768u;
        #pragma unroll
        for (int i = 0; i < 2; i++) {
            int idx = tid + i * 256;
            int r = idx >> 2, c = idx & 3;
            uint32_t dsw = (uint32_t)(r * 64 + ((c ^ ((r >> 1) & 3)) << 4));
            size_t asrc = (size_t)(bm + r) * HID + kc * 32 + c * 8;
            size_t wsrc = (size_t)(bn + r) * HID + kc * 32 + c * 8;
            cp16(stg + dsw,          Ahi + asrc);
            cp16(stg + 8192u + dsw,  Alo + asrc);
            cp16(stg + 16384u + dsw, Whi + wsrc);
            cp16(stg + 24576u + dsw, Wlo + wsrc);
        }
    };

    int raby[4], swa[4];
    #pragma unroll
    for (int mi = 0; mi < 4; mi++) {
        int r = wm * 64 + mi * 16 + (lane & 15);
        raby[mi] = r * 64;
        swa[mi] = (r >> 1) & 3;
    }
    const int hiA = lane >> 4;
    int rbby[2], swb[2];
    #pragma unroll
    for (int p = 0; p < 2; p++) {
        int n = wn * 32 + p * 16 + (((lane >> 3) >> 1) << 3) + (lane & 7);
        rbby[p] = n * 64;
        swb[p] = (n >> 1) & 3;
    }
    const int cbB = (lane >> 3) & 1;

    float acc[4][4][4];
    #pragma unroll
    for (int a = 0; a < 4; a++)
        #pragma unroll
        for (int bq = 0; bq < 4; bq++)
            #pragma unroll
            for (int q = 0; q < 4; q++) acc[a][bq][q] = 0.0f;

    #pragma unroll
    for (int s = 0; s < S - 1; s++) { if (s < na) load_stage(s, act[s]); cp_commit(); }

    #pragma unroll 1
    for (int ii = 0; ii < na; ii++) {
        cp_wait<S - 2>();
        __syncthreads();
        int ld = ii + S - 1;
        if (ld < na) load_stage(ld % S, act[ld]);
        cp_commit();

        uint32_t stg = sb + (uint32_t)(ii % S) * 32768u;
        #pragma unroll
        for (int k16 = 0; k16 < 2; k16++) {
            uint32_t a0[4][4], a1[4][4];
            #pragma unroll
            for (int mi = 0; mi < 4; mi++) {
                uint32_t off = (uint32_t)(raby[mi] + ((((k16 << 1) | hiA) ^ swa[mi]) << 4));
                ldm_x4(a0[mi], stg + off);
                ldm_x4(a1[mi], stg + 8192u + off);
            }
            #pragma unroll
            for (int p = 0; p < 2; p++) {
                uint32_t boff = (uint32_t)(rbby[p] + ((((k16 << 1) | cbB) ^ swb[p]) << 4));
                uint32_t bh[4];
                ldm_x4(bh, stg + 16384u + boff);
                #pragma unroll
                for (int mi = 0; mi < 4; mi++) {
                    mma_bf16(acc[mi][p * 2 + 0], a0[mi], &bh[0]);
                    mma_bf16(acc[mi][p * 2 + 1], a0[mi], &bh[2]);
                    mma_bf16(acc[mi][p * 2 + 0], a1[mi], &bh[0]);
                    mma_bf16(acc[mi][p * 2 + 1], a1[mi], &bh[2]);
                }
                uint32_t bl[4];
                ldm_x4(bl, stg + 24576u + boff);
                #pragma unroll
                for (int mi = 0; mi < 4; mi++) {
                    mma_bf16(acc[mi][p * 2 + 0], a0[mi], &bl[0]);
                    mma_bf16(acc[mi][p * 2 + 1], a0[mi], &bl[2]);
                }
            }
        }
    }
    cp_wait<0>();

    const int r0 = bm + wm * 64 + (lane >> 2);
    const int cbase = bn + wn * 32 + (lane & 3) * 2;
    #pragma unroll
    for (int mi = 0; mi < 4; mi++) {
        #pragma unroll
        for (int nj = 0; nj < 4; nj++) {
            int col = cbase + nj * 8;
            float b0 = bias[col], b1 = bias[col + 1];
            float2 v0 = {acc[mi][nj][0] + b0, acc[mi][nj][1] + b1};
            float2 v1 = {acc[mi][nj][2] + b0, acc[mi][nj][3] + b1};
            *(float2*)(C + (size_t)(r0 + mi * 16) * NOUT + col)     = v0;
            *(float2*)(C + (size_t)(r0 + mi * 16 + 8) * NOUT + col) = v1;
        }
    }
}

// ---------------------------------------------------------------------------
// Fused log_px + forward chain. 16 lanes/batch, 2 batches/warp.
// ---------------------------------------------------------------------------
__global__ void __launch_bounds__(128) chain_kernel(
    const float* __restrict__ x, const float* __restrict__ theta,
    const float* __restrict__ ulpa, float* __restrict__ out)
{
    __shared__ float s_lpa[255 * 4];
    for (int d = threadIdx.x; d < 255; d += 128) {
        float u0 = ulpa[d * 4 + 0], u1 = ulpa[d * 4 + 1];
        float u2 = ulpa[d * 4 + 2], u3 = ulpa[d * 4 + 3];
        float m = fmaxf(fmaxf(u0, u1), fmaxf(u2, u3));
        float s = expf(u0 - m) + expf(u1 - m) + expf(u2 - m) + expf(u3 - m);
        float lse = m + logf(s);
        s_lpa[d * 4 + 0] = u0 - lse;
        s_lpa[d * 4 + 1] = u1 - lse;
        s_lpa[d * 4 + 2] = u2 - lse;
        s_lpa[d * 4 + 3] = u3 - lse;
    }
    __syncthreads();

    const int lane = threadIdx.x & 31;
    const int wid  = threadIdx.x >> 5;
    const int half = lane >> 4;
    const int l    = lane & 15;
    const int i    = l >> 2, j = l & 3;
    const int b    = (blockIdx.x * 4 + wid) * 2 + half;

    const unsigned FULL = 0xffffffffu;
    const float NL = -0.91893853320467274178f;  // -0.5*log(2*pi)

    const float* th = theta + (size_t)b * NOUT;
    const float* xb = x + (size_t)b * DIN;

    float carry;
    {   // d = 0
        float mu = __ldg(th + l), ls = __ldg(th + 16 + l);
        float xd = __ldg(xb);
        float sd = __expf(ls) + 0.01f;
        float z = __fdividef(xd - mu, sd);
        float lp = fmaf(-0.5f * z, z, NL) - __logf(sd);
        float v = lp + s_lpa[j];
        carry = __shfl_sync(FULL, v, half * 16 + j);
    }
    float mu = __ldg(th + 32 + l), ls = __ldg(th + 48 + l);
    float xd = __ldg(xb + 1);
    #pragma unroll 1
    for (int d = 1; d < 255; d++) {
        float nmu = __ldg(th + (d + 1) * 32 + l);
        float nls = __ldg(th + (d + 1) * 32 + 16 + l);
        float nxd = __ldg(xb + d + 1);
        float sd = __expf(ls) + 0.01f;
        float z = __fdividef(xd - mu, sd);
        float lp = fmaf(-0.5f * z, z, NL) - __logf(sd);
        float ci = __shfl_sync(FULL, carry, half * 16 + i);
        float tv = ci + lp + s_lpa[d * 4 + j];
        float m = fmaxf(tv, __shfl_xor_sync(FULL, tv, 4));
        m = fmaxf(m, __shfl_xor_sync(FULL, m, 8));
        float s = __expf(tv - m);
        s += __shfl_xor_sync(FULL, s, 4);
        s += __shfl_xor_sync(FULL, s, 8);
        carry = m + __logf(s);
        mu = nmu; ls = nls; xd = nxd;
    }
    {   // d = 255
        float sd = __expf(ls) + 0.01f;
        float z = __fdividef(xd - mu, sd);
        float lp = fmaf(-0.5f * z, z, NL) - __logf(sd);
        float ci = __shfl_sync(FULL, carry, half * 16 + i);
        float tv = (j == 0) ? (ci + lp) : -1e30f;
        float m = fmaxf(tv, __shfl_xor_sync(FULL, tv, 1));
        m = fmaxf(m, __shfl_xor_sync(FULL, m, 2));
        m = fmaxf(m, __shfl_xor_sync(FULL, m, 4));
        m = fmaxf(m, __shfl_xor_sync(FULL, m, 8));
        float s = __expf(tv - m);
        s += __shfl_xor_sync(FULL, s, 1);
        s += __shfl_xor_sync(FULL, s, 2);
        s += __shfl_xor_sync(FULL, s, 4);
        s += __shfl_xor_sync(FULL, s, 8);
        if (l == 0) out[b] = m + __logf(s);
    }
}

// ---------------------------------------------------------------------------
// kernel_launch
// ---------------------------------------------------------------------------
extern "C" void kernel_launch(void* const* d_in, const int* in_sizes, int n_in,
                              void* d_out, int out_size)
{
    const float* x    = (const float*)d_in[0];
    const float* W0   = (const float*)d_in[1];
    const float* b0   = (const float*)d_in[2];
    const float* W1   = (const float*)d_in[3];
    const float* b1   = (const float*)d_in[4];
    const float* W2   = (const float*)d_in[5];
    const float* b2   = (const float*)d_in[6];
    const float* Wout = (const float*)d_in[7];
    const float* bout = (const float*)d_in[8];
    const float* ulpa = (const float*)d_in[9];

    float* out   = (float*)d_out;
    float* theta = out + BATCH;

    bf16 *xhi, *xlo, *w0hi, *w0lo, *w1hi, *w1lo, *w2hi, *w2lo;
    bf16 *h0hi, *h0lo, *h1hi, *h1lo, *h2hi, *h2lo, *whi, *wlo;
    cudaGetSymbolAddress((void**)&xhi, g_xhi);   cudaGetSymbolAddress((void**)&xlo, g_xlo);
    cudaGetSymbolAddress((void**)&w0hi, g_w0hi); cudaGetSymbolAddress((void**)&w0lo, g_w0lo);
    cudaGetSymbolAddress((void**)&w1hi, g_w1hi); cudaGetSymbolAddress((void**)&w1lo, g_w1lo);
    cudaGetSymbolAddress((void**)&w2hi, g_w2hi); cudaGetSymbolAddress((void**)&w2lo, g_w2lo);
    cudaGetSymbolAddress((void**)&h0hi, g_h0hi); cudaGetSymbolAddress((void**)&h0lo, g_h0lo);
    cudaGetSymbolAddress((void**)&h1hi, g_h1hi); cudaGetSymbolAddress((void**)&h1lo, g_h1lo);
    cudaGetSymbolAddress((void**)&h2hi, g_h2hi); cudaGetSymbolAddress((void**)&h2lo, g_h2lo);
    cudaGetSymbolAddress((void**)&whi, g_whi);   cudaGetSymbolAddress((void**)&wlo, g_wlo);

    cudaFuncSetAttribute(gemm_mma_kernel,
                         cudaFuncAttributeMaxDynamicSharedMemorySize, 98304);
    cudaFuncSetAttribute(layer_kernel<DIN, 0>,
                         cudaFuncAttributeMaxDynamicSharedMemorySize, 36864);
    cudaFuncSetAttribute(layer_kernel<HID, 1>,
                         cudaFuncAttributeMaxDynamicSharedMemorySize, 36864);

    split_wout_kernel<<<NOUT * HID / 4 / 256, 256>>>(Wout);
    prep_kernel<<<896, 256>>>(x, W0, W1, W2);

    layer_kernel<DIN, 0><<<dim3(HID / 64, BATCH / 32), 128, 36864>>>(
        xhi, xlo, w0hi, w0lo, b0, h0hi, h0lo);
    layer_kernel<HID, 1><<<dim3(HID / 64, BATCH / 32), 128, 36864>>>(
        h0hi, h0lo, w1hi, w1lo, b1, h1hi, h1lo);
    layer_kernel<HID, 1><<<dim3(HID / 64, BATCH / 32), 128, 36864>>>(
        h1hi, h1lo, w2hi, w2lo, b2, h2hi, h2lo);

    gemm_mma_kernel<<<dim3(NOUT / 128, BATCH / 128), 256, 98304>>>(
        h2hi, h2lo, whi, wlo, bout, theta);

    chain_kernel<<<BATCH / 8, 128>>>(x, theta, ulpa, out);
}